// round 3
// baseline (speedup 1.0000x reference)
#include <cuda_runtime.h>
#include <math.h>

#define BATCH   16
#define C_DIM   384
#define NPIX    784
#define T_TOK   (BATCH*NPIX)      // 12544
#define HEADS   8
#define HDIM    48
#define FFN_DIM 1536
#define BN_EPS  1e-5f

// ---------------- scratch (static device globals; no allocation) ----------------
__device__ float g_tmp[BATCH*C_DIM*NPIX];   // conv output, NCHW
__device__ float g_lx [T_TOK*C_DIM];        // token-major [t][c]
__device__ float g_q  [T_TOK*C_DIM];
__device__ float g_k  [T_TOK*C_DIM];
__device__ float g_v  [T_TOK*C_DIM];
__device__ float g_ao [T_TOK*C_DIM];        // attention output
__device__ float g_r  [T_TOK*C_DIM];        // residual (proj + lx)
__device__ float g_h  [T_TOK*C_DIM];        // bn2(residual)
__device__ float g_f1 [T_TOK*FFN_DIM];      // ffn1 output

// ---------------- depthwise 3x3 conv + BN1 (NCHW -> NCHW tmp) ----------------
__global__ void dwconv_bn_kernel(const float* __restrict__ x,
                                 const float* __restrict__ w,
                                 const float* __restrict__ bconv,
                                 const float* __restrict__ bg,
                                 const float* __restrict__ bb,
                                 const float* __restrict__ bm,
                                 const float* __restrict__ bv)
{
    int gid = blockIdx.x * blockDim.x + threadIdx.x;
    if (gid >= BATCH*C_DIM*NPIX) return;
    int hw = gid % NPIX;
    int bc = gid / NPIX;
    int c  = bc % C_DIM;
    int yy = hw / 28, xx = hw % 28;
    const float* xp = x + (size_t)bc * NPIX;
    const float* wp = w + c * 9;
    float s = 0.f;
#pragma unroll
    for (int ky = 0; ky < 3; ky++) {
        int y = yy + ky - 1;
        if ((unsigned)y < 28u) {
#pragma unroll
            for (int kx = 0; kx < 3; kx++) {
                int x2 = xx + kx - 1;
                if ((unsigned)x2 < 28u) s += wp[ky*3+kx] * xp[y*28 + x2];
            }
        }
    }
    s += bconv[c];
    float inv = rsqrtf(bv[c] + BN_EPS);
    g_tmp[gid] = (s - bm[c]) * inv * bg[c] + bb[c];
}

// ---------------- transpose NCHW -> token-major [t][c] ----------------
__global__ void to_tokens_kernel()
{
    __shared__ float tile[32][33];
    int b   = blockIdx.z;
    int hw0 = blockIdx.x * 32;
    int c0  = blockIdx.y * 32;
    int tx = threadIdx.x, ty = threadIdx.y;   // 32 x 8
#pragma unroll
    for (int j = 0; j < 32; j += 8) {
        int c = c0 + ty + j, hw = hw0 + tx;
        tile[ty + j][tx] = (hw < NPIX) ? g_tmp[((size_t)b*C_DIM + c)*NPIX + hw] : 0.f;
    }
    __syncthreads();
#pragma unroll
    for (int j = 0; j < 32; j += 8) {
        int hw = hw0 + ty + j, c = c0 + tx;
        if (hw < NPIX)
            g_lx[((size_t)b*NPIX + hw)*C_DIM + c] = tile[tx][ty + j];
    }
}

// ---------------- generic SGEMM: out[t][o] = sum_k A[t][k]*W[o][k] + epilogue ----------------
// MODE 0: + bias                                (qkv)
// MODE 1: + bias + res -> out(=R); out2 = BN2   (proj)
// MODE 2: gelu(+bias)                           (ffn1)
// MODE 3: + bias + res, write NCHW to out       (ffn2, final)
template<int MODE>
__global__ void __launch_bounds__(256)
sgemm_kernel(const float* __restrict__ A, const float* __restrict__ W,
             const float* __restrict__ bias,
             const float* __restrict__ res,
             const float* __restrict__ bng, const float* __restrict__ bnb,
             const float* __restrict__ bnm, const float* __restrict__ bnv,
             float* __restrict__ out, float* __restrict__ out2,
             int K, int N)
{
    __shared__ float As[8][128];
    __shared__ float Bs[8][128];

    int tid = threadIdx.x;
    int bx = blockIdx.x, by = blockIdx.y;

    int sr = tid >> 1;          // 0..127
    int kc = (tid & 1) * 4;     // 0 or 4
    const float* Ap = A + (size_t)(by*128 + sr) * K + kc;
    const float* Wp = W + (size_t)(bx*128 + sr) * K + kc;

    float4 a = *(const float4*)Ap;
    float4 b = *(const float4*)Wp;

    int tx = tid & 15, ty = tid >> 4;
    float acc[8][8];
#pragma unroll
    for (int i = 0; i < 8; i++)
#pragma unroll
        for (int j = 0; j < 8; j++) acc[i][j] = 0.f;

    for (int kt = 0; kt < K; kt += 8) {
        // store current tile (transposed)
        As[kc+0][sr] = a.x; As[kc+1][sr] = a.y; As[kc+2][sr] = a.z; As[kc+3][sr] = a.w;
        Bs[kc+0][sr] = b.x; Bs[kc+1][sr] = b.y; Bs[kc+2][sr] = b.z; Bs[kc+3][sr] = b.w;
        __syncthreads();

        if (kt + 8 < K) {
            a = *(const float4*)(Ap + kt + 8);
            b = *(const float4*)(Wp + kt + 8);
        }

#pragma unroll
        for (int k = 0; k < 8; k++) {
            float ra[8], rb[8];
#pragma unroll
            for (int i = 0; i < 8; i++) ra[i] = As[k][ty*8 + i];
#pragma unroll
            for (int j = 0; j < 8; j++) rb[j] = Bs[k][tx*8 + j];
#pragma unroll
            for (int i = 0; i < 8; i++)
#pragma unroll
                for (int j = 0; j < 8; j++) acc[i][j] += ra[i] * rb[j];
        }
        __syncthreads();
    }

    int t0 = by*128 + ty*8;
    int o0 = bx*128 + tx*8;

#pragma unroll
    for (int i = 0; i < 8; i++) {
        int t = t0 + i;
#pragma unroll
        for (int j = 0; j < 8; j++) {
            int o = o0 + j;
            float val = acc[i][j] + bias[o];
            if (MODE == 0) {
                out[(size_t)t*N + o] = val;
            } else if (MODE == 1) {
                val += res[(size_t)t*C_DIM + o];
                out[(size_t)t*C_DIM + o] = val;
                float inv = rsqrtf(bnv[o] + BN_EPS);
                out2[(size_t)t*C_DIM + o] = (val - bnm[o]) * inv * bng[o] + bnb[o];
            } else if (MODE == 2) {
                out[(size_t)t*N + o] = 0.5f * val * (1.0f + erff(val * 0.7071067811865475f));
            } else { // MODE 3: final, NCHW
                val += res[(size_t)t*C_DIM + o];
                int bb2 = t / NPIX;
                int n   = t - bb2 * NPIX;
                out[((size_t)bb2*C_DIM + o)*NPIX + n] = val;
            }
        }
    }
}

// ---------------- fused attention: per (b, h, 56-query block) ----------------
#define TQ  56
#define TKK 128
#define QS_STRIDE 60
#define KS_STRIDE 132
#define VS_STRIDE 52
// smem floats: S 56*784, Qs 48*60, KV max(48*132, 128*52)=6656, rinv 56
#define ATTN_S_FLOATS   (TQ*NPIX)
#define ATTN_QS_FLOATS  (HDIM*QS_STRIDE)
#define ATTN_KV_FLOATS  (TKK*VS_STRIDE)
#define ATTN_SMEM_BYTES ((ATTN_S_FLOATS + ATTN_QS_FLOATS + ATTN_KV_FLOATS + TQ) * 4)

__global__ void __launch_bounds__(256)
attn_kernel(const float* __restrict__ Qt, const float* __restrict__ Kt,
            const float* __restrict__ Vt, float* __restrict__ AO)
{
    extern __shared__ float sm[];
    float* S    = sm;                                  // [56][784]
    float* Qs   = S + ATTN_S_FLOATS;                   // [48][60] : Qs[d][i]
    float* KV   = Qs + ATTN_QS_FLOATS;                 // Ks[d][132] / Vs[mm][52]
    float* rinv = KV + ATTN_KV_FLOATS;                 // [56]

    int tid = threadIdx.x;
    int qb = blockIdx.x, h = blockIdx.y, b = blockIdx.z;
    int q0 = qb * TQ;
    const float scale = 0.14433756729740643f;          // 48^-0.5

    // load + scale Q tile (transposed: Qs[d][i])
    for (int idx = tid; idx < TQ*12; idx += 256) {
        int i = idx / 12, d4 = (idx % 12) * 4;
        float4 qv = *(const float4*)&Qt[((size_t)(b*NPIX + q0 + i))*C_DIM + h*HDIM + d4];
        Qs[(d4+0)*QS_STRIDE + i] = qv.x * scale;
        Qs[(d4+1)*QS_STRIDE + i] = qv.y * scale;
        Qs[(d4+2)*QS_STRIDE + i] = qv.z * scale;
        Qs[(d4+3)*QS_STRIDE + i] = qv.w * scale;
    }

    int ty = tid >> 5, tx = tid & 31;   // 8 x 32

    // ---- phase A: S = Q K^T ----
    for (int n0 = 0; n0 < NPIX; n0 += TKK) {
        int cols = min(TKK, NPIX - n0);
        __syncthreads();
        for (int idx = tid; idx < TKK*12; idx += 256) {
            int mm = idx / 12, d4 = (idx % 12) * 4;
            if (mm < cols) {
                float4 kv = *(const float4*)&Kt[((size_t)(b*NPIX + n0 + mm))*C_DIM + h*HDIM + d4];
                KV[(d4+0)*KS_STRIDE + mm] = kv.x;
                KV[(d4+1)*KS_STRIDE + mm] = kv.y;
                KV[(d4+2)*KS_STRIDE + mm] = kv.z;
                KV[(d4+3)*KS_STRIDE + mm] = kv.w;
            } else {
                KV[(d4+0)*KS_STRIDE + mm] = 0.f;
                KV[(d4+1)*KS_STRIDE + mm] = 0.f;
                KV[(d4+2)*KS_STRIDE + mm] = 0.f;
                KV[(d4+3)*KS_STRIDE + mm] = 0.f;
            }
        }
        __syncthreads();

        float acc[7][4];
#pragma unroll
        for (int r = 0; r < 7; r++)
#pragma unroll
            for (int c = 0; c < 4; c++) acc[r][c] = 0.f;

#pragma unroll 6
        for (int k = 0; k < HDIM; k++) {
            float4 rb = *(const float4*)&KV[k*KS_STRIDE + tx*4];
            float ra[7];
#pragma unroll
            for (int r = 0; r < 7; r++) ra[r] = Qs[k*QS_STRIDE + ty*7 + r];
#pragma unroll
            for (int r = 0; r < 7; r++) {
                acc[r][0] += ra[r] * rb.x;
                acc[r][1] += ra[r] * rb.y;
                acc[r][2] += ra[r] * rb.z;
                acc[r][3] += ra[r] * rb.w;
            }
        }
#pragma unroll
        for (int r = 0; r < 7; r++) {
#pragma unroll
            for (int c = 0; c < 4; c++) {
                int m = n0 + tx*4 + c;
                if (m < NPIX) S[(ty*7 + r)*NPIX + m] = acc[r][c];
            }
        }
    }
    __syncthreads();

    // ---- softmax (unnormalized exp; 1/sum recorded) ----
    {
        int w = tid >> 5, lane = tid & 31;
#pragma unroll
        for (int j = 0; j < 7; j++) {
            int i = w + 8*j;
            float mx = -1e30f;
            for (int m = lane; m < NPIX; m += 32) mx = fmaxf(mx, S[i*NPIX + m]);
#pragma unroll
            for (int off = 16; off > 0; off >>= 1)
                mx = fmaxf(mx, __shfl_xor_sync(0xffffffffu, mx, off));
            float sum = 0.f;
            for (int m = lane; m < NPIX; m += 32) {
                float e = __expf(S[i*NPIX + m] - mx);
                S[i*NPIX + m] = e;
                sum += e;
            }
#pragma unroll
            for (int off = 16; off > 0; off >>= 1)
                sum += __shfl_xor_sync(0xffffffffu, sum, off);
            if (lane == 0) rinv[i] = 1.0f / sum;
        }
    }

    // ---- phase B: O = P V ----
    float ob[12];
#pragma unroll
    for (int d = 0; d < 12; d++) ob[d] = 0.f;
    int i  = tid % TQ;
    int dg = tid / TQ;            // 0..3 valid
    bool active = tid < 4*TQ;     // 224 threads

    for (int n0 = 0; n0 < NPIX; n0 += TKK) {
        int cols = min(TKK, NPIX - n0);
        __syncthreads();
        for (int idx = tid; idx < TKK*12; idx += 256) {
            int mm = idx / 12, d4 = (idx % 12) * 4;
            if (mm < cols) {
                float4 vv = *(const float4*)&Vt[((size_t)(b*NPIX + n0 + mm))*C_DIM + h*HDIM + d4];
                *(float4*)&KV[mm*VS_STRIDE + d4] = vv;
            }
        }
        __syncthreads();
        if (active) {
            for (int mm = 0; mm < cols; mm += 4) {
                float4 p = *(const float4*)&S[i*NPIX + n0 + mm];
                float pv[4] = {p.x, p.y, p.z, p.w};
#pragma unroll
                for (int u = 0; u < 4; u++) {
                    const float* vrow = &KV[(mm + u)*VS_STRIDE + dg*12];
#pragma unroll
                    for (int d = 0; d < 12; d++) ob[d] += pv[u] * vrow[d];
                }
            }
        }
    }

    if (active) {
        float inv = rinv[i];
        float* op = &AO[((size_t)(b*NPIX + q0 + i))*C_DIM + h*HDIM + dg*12];
#pragma unroll
        for (int d = 0; d < 12; d++) op[d] = ob[d] * inv;
    }
}

// ---------------- host ----------------
extern "C" void kernel_launch(void* const* d_in, const int* in_sizes, int n_in,
                              void* d_out, int out_size)
{
    const float* x       = (const float*)d_in[0];
    const float* local_w = (const float*)d_in[1];
    const float* local_b = (const float*)d_in[2];
    const float* bn1_g   = (const float*)d_in[3];
    const float* bn1_b   = (const float*)d_in[4];
    const float* bn1_m   = (const float*)d_in[5];
    const float* bn1_v   = (const float*)d_in[6];
    const float* q_w     = (const float*)d_in[7];
    const float* q_b     = (const float*)d_in[8];
    const float* k_w     = (const float*)d_in[9];
    const float* k_b     = (const float*)d_in[10];
    const float* v_w     = (const float*)d_in[11];
    const float* v_b     = (const float*)d_in[12];
    const float* proj_w  = (const float*)d_in[13];
    const float* proj_b  = (const float*)d_in[14];
    const float* ffn1_w  = (const float*)d_in[15];
    const float* ffn1_b  = (const float*)d_in[16];
    const float* ffn2_w  = (const float*)d_in[17];
    const float* ffn2_b  = (const float*)d_in[18];
    const float* bn2_g   = (const float*)d_in[19];
    const float* bn2_b   = (const float*)d_in[20];
    const float* bn2_m   = (const float*)d_in[21];
    const float* bn2_v   = (const float*)d_in[22];

    float *lx, *q, *k, *v, *ao, *r, *h, *f1;
    cudaGetSymbolAddress((void**)&lx, g_lx);
    cudaGetSymbolAddress((void**)&q,  g_q);
    cudaGetSymbolAddress((void**)&k,  g_k);
    cudaGetSymbolAddress((void**)&v,  g_v);
    cudaGetSymbolAddress((void**)&ao, g_ao);
    cudaGetSymbolAddress((void**)&r,  g_r);
    cudaGetSymbolAddress((void**)&h,  g_h);
    cudaGetSymbolAddress((void**)&f1, g_f1);

    // 1. depthwise conv + BN1
    dwconv_bn_kernel<<<(BATCH*C_DIM*NPIX + 255)/256, 256>>>(
        x, local_w, local_b, bn1_g, bn1_b, bn1_m, bn1_v);

    // 2. NCHW -> token-major
    to_tokens_kernel<<<dim3(25, 12, BATCH), dim3(32, 8)>>>();

    dim3 g384(3, 98), g1536(12, 98);

    // 3. QKV
    sgemm_kernel<0><<<g384, 256>>>(lx, q_w, q_b, nullptr, nullptr, nullptr, nullptr, nullptr, q, nullptr, 384, 384);
    sgemm_kernel<0><<<g384, 256>>>(lx, k_w, k_b, nullptr, nullptr, nullptr, nullptr, nullptr, k, nullptr, 384, 384);
    sgemm_kernel<0><<<g384, 256>>>(lx, v_w, v_b, nullptr, nullptr, nullptr, nullptr, nullptr, v, nullptr, 384, 384);

    // 4. attention
    cudaFuncSetAttribute(attn_kernel, cudaFuncAttributeMaxDynamicSharedMemorySize, ATTN_SMEM_BYTES);
    attn_kernel<<<dim3(NPIX/TQ, HEADS, BATCH), 256, ATTN_SMEM_BYTES>>>(q, k, v, ao);

    // 5. proj + residual + BN2 (R, H)
    sgemm_kernel<1><<<g384, 256>>>(ao, proj_w, proj_b, lx, bn2_g, bn2_b, bn2_m, bn2_v, r, h, 384, 384);

    // 6. FFN1 + gelu
    sgemm_kernel<2><<<g1536, 256>>>(h, ffn1_w, ffn1_b, nullptr, nullptr, nullptr, nullptr, nullptr, f1, nullptr, 384, 1536);

    // 7. FFN2 + residual, write NCHW output
    sgemm_kernel<3><<<g384, 256>>>(f1, ffn2_w, ffn2_b, r, nullptr, nullptr, nullptr, nullptr, (float*)d_out, nullptr, 1536, 384);
}

// round 7
// speedup vs baseline: 1.5112x; 1.5112x over previous
#include <cuda_runtime.h>
#include <cuda_bf16.h>
#include <math.h>
#include <stdint.h>

typedef __nv_bfloat16 bf16;

#define BATCH   16
#define C_DIM   384
#define NPIX    784
#define T_TOK   (BATCH*NPIX)      // 12544
#define HEADS   8
#define HDIM    48
#define FFN_DIM 1536
#define BN_EPS  1e-5f

// ---------------- scratch (static device globals; no allocation) ----------------
__device__ float g_tmp[BATCH*C_DIM*NPIX];   // conv output, NCHW
__device__ float g_lx [T_TOK*C_DIM];        // token-major f32 (residual for proj)
__device__ bf16  g_lxh[T_TOK*C_DIM];
__device__ bf16  g_lxl[T_TOK*C_DIM];
__device__ float g_q  [T_TOK*C_DIM];
__device__ float g_k  [T_TOK*C_DIM];
__device__ float g_v  [T_TOK*C_DIM];
__device__ bf16  g_aoh[T_TOK*C_DIM];
__device__ bf16  g_aol[T_TOK*C_DIM];
__device__ float g_r  [T_TOK*C_DIM];        // residual (proj + lx), f32
__device__ bf16  g_hh [T_TOK*C_DIM];        // bn2(residual) hi/lo
__device__ bf16  g_hl [T_TOK*C_DIM];
__device__ bf16  g_f1h[T_TOK*FFN_DIM];      // ffn1 output hi/lo
__device__ bf16  g_f1l[T_TOK*FFN_DIM];
// weights hi/lo
__device__ bf16  g_qwh[C_DIM*C_DIM], g_qwl[C_DIM*C_DIM];
__device__ bf16  g_kwh[C_DIM*C_DIM], g_kwl[C_DIM*C_DIM];
__device__ bf16  g_vwh[C_DIM*C_DIM], g_vwl[C_DIM*C_DIM];
__device__ bf16  g_pwh[C_DIM*C_DIM], g_pwl[C_DIM*C_DIM];
__device__ bf16  g_w1h[FFN_DIM*C_DIM], g_w1l[FFN_DIM*C_DIM];
__device__ bf16  g_w2h[C_DIM*FFN_DIM], g_w2l[C_DIM*FFN_DIM];

// ======================= helpers =======================
__device__ __forceinline__ uint32_t smem_u32(const void* p) {
    return (uint32_t)__cvta_generic_to_shared(p);
}
__device__ __forceinline__ void split_bf16(float x, bf16& hi, bf16& lo) {
    hi = __float2bfloat16_rn(x);
    lo = __float2bfloat16_rn(x - __bfloat162float(hi));
}
__device__ __forceinline__ void ldsm4(uint32_t* r, uint32_t addr) {
    asm volatile("ldmatrix.sync.aligned.m8n8.x4.shared.b16 {%0,%1,%2,%3}, [%4];"
                 : "=r"(r[0]), "=r"(r[1]), "=r"(r[2]), "=r"(r[3]) : "r"(addr));
}
__device__ __forceinline__ void mma16816(float* c, const uint32_t* a, uint32_t b0, uint32_t b1) {
    asm volatile("mma.sync.aligned.m16n8k16.row.col.f32.bf16.bf16.f32 "
                 "{%0,%1,%2,%3}, {%4,%5,%6,%7}, {%8,%9}, {%0,%1,%2,%3};"
                 : "+f"(c[0]), "+f"(c[1]), "+f"(c[2]), "+f"(c[3])
                 : "r"(a[0]), "r"(a[1]), "r"(a[2]), "r"(a[3]), "r"(b0), "r"(b1));
}

// ---------------- f32 -> bf16 hi/lo conversion (weights) ----------------
__global__ void cvt_kernel(const float* __restrict__ src, bf16* __restrict__ h,
                           bf16* __restrict__ l, int n)
{
    int i = blockIdx.x * 256 + threadIdx.x;
    if (i < n) { bf16 hi, lo; split_bf16(src[i], hi, lo); h[i] = hi; l[i] = lo; }
}

// ---------------- depthwise 3x3 conv + BN1 (NCHW -> NCHW tmp) ----------------
__global__ void dwconv_bn_kernel(const float* __restrict__ x,
                                 const float* __restrict__ w,
                                 const float* __restrict__ bconv,
                                 const float* __restrict__ bg,
                                 const float* __restrict__ bb,
                                 const float* __restrict__ bm,
                                 const float* __restrict__ bv)
{
    int gid = blockIdx.x * blockDim.x + threadIdx.x;
    if (gid >= BATCH*C_DIM*NPIX) return;
    int hw = gid % NPIX;
    int bc = gid / NPIX;
    int c  = bc % C_DIM;
    int yy = hw / 28, xx = hw % 28;
    const float* xp = x + (size_t)bc * NPIX;
    const float* wp = w + c * 9;
    float s = 0.f;
#pragma unroll
    for (int ky = 0; ky < 3; ky++) {
        int y = yy + ky - 1;
        if ((unsigned)y < 28u) {
#pragma unroll
            for (int kx = 0; kx < 3; kx++) {
                int x2 = xx + kx - 1;
                if ((unsigned)x2 < 28u) s += wp[ky*3+kx] * xp[y*28 + x2];
            }
        }
    }
    s += bconv[c];
    float inv = rsqrtf(bv[c] + BN_EPS);
    g_tmp[gid] = (s - bm[c]) * inv * bg[c] + bb[c];
}

// ---------------- transpose NCHW -> token-major [t][c] (+ bf16 hi/lo) ----------------
__global__ void to_tokens_kernel()
{
    __shared__ float tile[32][33];
    int b   = blockIdx.z;
    int hw0 = blockIdx.x * 32;
    int c0  = blockIdx.y * 32;
    int tx = threadIdx.x, ty = threadIdx.y;   // 32 x 8
#pragma unroll
    for (int j = 0; j < 32; j += 8) {
        int c = c0 + ty + j, hw = hw0 + tx;
        tile[ty + j][tx] = (hw < NPIX) ? g_tmp[((size_t)b*C_DIM + c)*NPIX + hw] : 0.f;
    }
    __syncthreads();
#pragma unroll
    for (int j = 0; j < 32; j += 8) {
        int hw = hw0 + ty + j, c = c0 + tx;
        if (hw < NPIX) {
            float v = tile[tx][ty + j];
            size_t idx = ((size_t)b*NPIX + hw)*C_DIM + c;
            g_lx[idx] = v;
            bf16 hi, lo; split_bf16(v, hi, lo);
            g_lxh[idx] = hi; g_lxl[idx] = lo;
        }
    }
}

// ======================= mma.sync split-bf16 GEMM =======================
// D[t][o] = sum_k A[t][k]*W[o][k], A=Ah+Al, W=Wh+Wl (3 MMAs: hh, hl, lh)
// CTA tile 128x128, 8 warps in 4(m) x 2(n), warp tile 32x64, K chunk 64.
// MODE 0: +bias -> f32                         (qkv)
// MODE 1: +bias+res -> f32 out(r); BN2 -> hi/lo (proj)
// MODE 2: gelu(+bias) -> hi/lo                 (ffn1)
// MODE 3: +bias+res -> NCHW f32                (ffn2 final)
#define KC    64
#define ASTR  72                             // bf16 row stride (144B) - ldmatrix conflict-free
#define TILE_ELE (128*ASTR)
#define GEMM_SMEM (4*TILE_ELE*2)             // 73728 B

__device__ __forceinline__ void load_tile(const bf16* __restrict__ src, int rbase, int K, int k0,
                                          bf16* __restrict__ dst)
{
    int tid = threadIdx.x;
#pragma unroll
    for (int i = 0; i < 4; ++i) {
        int ch = tid + i*256;             // 0..1023
        int r = ch >> 3, c = ch & 7;
        uint4 v = *(const uint4*)(src + (size_t)(rbase + r)*K + k0 + c*8);
        *(uint4*)(dst + r*ASTR + c*8) = v;
    }
}

template<int MODE>
__global__ void __launch_bounds__(256, 2)
gemm_mma(const bf16* __restrict__ Ah, const bf16* __restrict__ Al,
         const bf16* __restrict__ Wh, const bf16* __restrict__ Wl,
         const float* __restrict__ bias, const float* __restrict__ res,
         const float* __restrict__ bng, const float* __restrict__ bnb,
         const float* __restrict__ bnm, const float* __restrict__ bnv,
         float* __restrict__ outf, bf16* __restrict__ oh, bf16* __restrict__ ol,
         int K, int N)
{
    extern __shared__ __align__(16) bf16 smb[];
    bf16* sAh = smb;
    bf16* sAl = smb + TILE_ELE;
    bf16* sWh = smb + 2*TILE_ELE;
    bf16* sWl = smb + 3*TILE_ELE;

    const int tid = threadIdx.x;
    const int wid = tid >> 5, l = tid & 31;
    const int wm = wid & 3, wn = wid >> 2;    // warp tile: rows wm*32, cols wn*64
    const int t0 = blockIdx.y * 128;
    const int o0 = blockIdx.x * 128;

    float acc[2][8][4];
#pragma unroll
    for (int f = 0; f < 2; f++)
#pragma unroll
        for (int g = 0; g < 8; g++)
#pragma unroll
            for (int i = 0; i < 4; i++) acc[f][g][i] = 0.f;

    // ldmatrix lane address components (element offsets within a tile)
    const int arow = l & 15;
    const int acol = (l >> 4) * 8;
    const int brow = ((l >> 4) << 3) + (l & 7);
    const int bcol = ((l >> 3) & 1) * 8;
    const uint32_t baseAh = smem_u32(sAh), baseAl = smem_u32(sAl);
    const uint32_t baseWh = smem_u32(sWh), baseWl = smem_u32(sWl);

    const int nch = K / KC;
    for (int ch = 0; ch < nch; ++ch) {
        __syncthreads();
        const int k0g = ch * KC;
        load_tile(Ah, t0, K, k0g, sAh);
        load_tile(Al, t0, K, k0g, sAl);
        load_tile(Wh, o0, K, k0g, sWh);
        load_tile(Wl, o0, K, k0g, sWl);
        __syncthreads();

#pragma unroll
        for (int kk = 0; kk < 4; ++kk) {
            const int k0 = kk * 16;
            uint32_t ah[2][4], al2[2][4];
#pragma unroll
            for (int f = 0; f < 2; ++f) {
                uint32_t off = (uint32_t)(((wm*32 + f*16 + arow)*ASTR + k0 + acol) * 2);
                ldsm4(ah[f],  baseAh + off);
                ldsm4(al2[f], baseAl + off);
            }
#pragma unroll
            for (int gp = 0; gp < 4; ++gp) {
                uint32_t bh[4], bl[4];
                uint32_t off = (uint32_t)(((wn*64 + gp*16 + brow)*ASTR + k0 + bcol) * 2);
                ldsm4(bh, baseWh + off);
                ldsm4(bl, baseWl + off);
#pragma unroll
                for (int f = 0; f < 2; ++f) {
                    mma16816(acc[f][2*gp],   ah[f],  bh[0], bh[1]);
                    mma16816(acc[f][2*gp+1], ah[f],  bh[2], bh[3]);
                    mma16816(acc[f][2*gp],   ah[f],  bl[0], bl[1]);
                    mma16816(acc[f][2*gp+1], ah[f],  bl[2], bl[3]);
                    mma16816(acc[f][2*gp],   al2[f], bh[0], bh[1]);
                    mma16816(acc[f][2*gp+1], al2[f], bh[2], bh[3]);
                }
            }
        }
    }

    // ---- epilogue: c0,c1 -> row l/4; c2,c3 -> row l/4+8; cols (l%4)*2,+1 ----
    const int row_in = l >> 2, col_in = (l & 3) * 2;
#pragma unroll
    for (int f = 0; f < 2; ++f) {
        const int tb = t0 + wm*32 + f*16 + row_in;
#pragma unroll
        for (int g = 0; g < 8; ++g) {
            const int o = o0 + wn*64 + g*8 + col_in;
#pragma unroll
            for (int hhalf = 0; hhalf < 2; ++hhalf) {
                const int t = tb + hhalf*8;
                const float c0 = acc[f][g][hhalf*2 + 0];
                const float c1 = acc[f][g][hhalf*2 + 1];
                if (MODE == 0) {
                    float2 v2 = make_float2(c0 + bias[o], c1 + bias[o+1]);
                    *(float2*)&outf[(size_t)t*N + o] = v2;
                } else if (MODE == 1) {
#pragma unroll
                    for (int u = 0; u < 2; ++u) {
                        int oo = o + u;
                        size_t idx = (size_t)t*C_DIM + oo;
                        float val = (u ? c1 : c0) + bias[oo] + res[idx];
                        outf[idx] = val;
                        float inv = rsqrtf(bnv[oo] + BN_EPS);
                        float hb = (val - bnm[oo]) * inv * bng[oo] + bnb[oo];
                        bf16 hi, lo; split_bf16(hb, hi, lo);
                        oh[idx] = hi; ol[idx] = lo;
                    }
                } else if (MODE == 2) {
#pragma unroll
                    for (int u = 0; u < 2; ++u) {
                        int oo = o + u;
                        float val = (u ? c1 : c0) + bias[oo];
                        float ge = 0.5f * val * (1.0f + erff(val * 0.7071067811865475f));
                        size_t idx = (size_t)t*N + oo;
                        bf16 hi, lo; split_bf16(ge, hi, lo);
                        oh[idx] = hi; ol[idx] = lo;
                    }
                } else { // MODE 3: NCHW final
                    const int bb2 = t / NPIX;
                    const int nn  = t - bb2 * NPIX;
#pragma unroll
                    for (int u = 0; u < 2; ++u) {
                        int oo = o + u;
                        float val = (u ? c1 : c0) + bias[oo] + res[(size_t)t*C_DIM + oo];
                        outf[((size_t)bb2*C_DIM + oo)*NPIX + nn] = val;
                    }
                }
            }
        }
    }
}

// ---------------- fused attention: per (b, h, 56-query block) ----------------
#define TQ  56
#define TKK 128
#define SSTR 788                 // S row stride (floats); 788/4=197 odd -> conflict-free float4
#define QS_STRIDE 60
#define KS_STRIDE 132
#define VS_STRIDE 52
#define ATTN_S_FLOATS   (TQ*SSTR)
#define ATTN_QS_FLOATS  (HDIM*QS_STRIDE)
#define ATTN_KV_FLOATS  (TKK*VS_STRIDE)
#define ATTN_SMEM_BYTES ((ATTN_S_FLOATS + ATTN_QS_FLOATS + ATTN_KV_FLOATS + TQ) * 4)

__global__ void __launch_bounds__(256)
attn_kernel(const float* __restrict__ Qt, const float* __restrict__ Kt,
            const float* __restrict__ Vt, bf16* __restrict__ AOh, bf16* __restrict__ AOl)
{
    extern __shared__ float sm[];
    float* S    = sm;                                  // [56][SSTR]
    float* Qs   = S + ATTN_S_FLOATS;                   // [48][60] : Qs[d][i]
    float* KV   = Qs + ATTN_QS_FLOATS;                 // Ks[d][132] / Vs[mm][52]
    float* rinv = KV + ATTN_KV_FLOATS;                 // [56]

    int tid = threadIdx.x;
    int qb = blockIdx.x, h = blockIdx.y, b = blockIdx.z;
    int q0 = qb * TQ;
    const float scale = 0.14433756729740643f;          // 48^-0.5

    for (int idx = tid; idx < TQ*12; idx += 256) {
        int i = idx / 12, d4 = (idx % 12) * 4;
        float4 qv = *(const float4*)&Qt[((size_t)(b*NPIX + q0 + i))*C_DIM + h*HDIM + d4];
        Qs[(d4+0)*QS_STRIDE + i] = qv.x * scale;
        Qs[(d4+1)*QS_STRIDE + i] = qv.y * scale;
        Qs[(d4+2)*QS_STRIDE + i] = qv.z * scale;
        Qs[(d4+3)*QS_STRIDE + i] = qv.w * scale;
    }

    int ty = tid >> 5, tx = tid & 31;   // 8 x 32

    // ---- phase A: S = Q K^T ----
    for (int n0 = 0; n0 < NPIX; n0 += TKK) {
        int cols = min(TKK, NPIX - n0);
        __syncthreads();
        for (int idx = tid; idx < TKK*12; idx += 256) {
            int mm = idx / 12, d4 = (idx % 12) * 4;
            if (mm < cols) {
                float4 kv = *(const float4*)&Kt[((size_t)(b*NPIX + n0 + mm))*C_DIM + h*HDIM + d4];
                KV[(d4+0)*KS_STRIDE + mm] = kv.x;
                KV[(d4+1)*KS_STRIDE + mm] = kv.y;
                KV[(d4+2)*KS_STRIDE + mm] = kv.z;
                KV[(d4+3)*KS_STRIDE + mm] = kv.w;
            } else {
                KV[(d4+0)*KS_STRIDE + mm] = 0.f;
                KV[(d4+1)*KS_STRIDE + mm] = 0.f;
                KV[(d4+2)*KS_STRIDE + mm] = 0.f;
                KV[(d4+3)*KS_STRIDE + mm] = 0.f;
            }
        }
        __syncthreads();

        float acc[7][4];
#pragma unroll
        for (int r = 0; r < 7; r++)
#pragma unroll
            for (int c = 0; c < 4; c++) acc[r][c] = 0.f;

#pragma unroll 6
        for (int k = 0; k < HDIM; k++) {
            float4 rb = *(const float4*)&KV[k*KS_STRIDE + tx*4];
            float ra[7];
#pragma unroll
            for (int r = 0; r < 7; r++) ra[r] = Qs[k*QS_STRIDE + ty*7 + r];
#pragma unroll
            for (int r = 0; r < 7; r++) {
                acc[r][0] += ra[r] * rb.x;
                acc[r][1] += ra[r] * rb.y;
                acc[r][2] += ra[r] * rb.z;
                acc[r][3] += ra[r] * rb.w;
            }
        }
        if (tx*4 < cols) {
#pragma unroll
            for (int r = 0; r < 7; r++) {
                float4 v = make_float4(acc[r][0], acc[r][1], acc[r][2], acc[r][3]);
                *(float4*)&S[(ty*7 + r)*SSTR + n0 + tx*4] = v;
            }
        }
    }
    __syncthreads();

    // ---- softmax (unnormalized exp; 1/sum recorded) ----
    {
        int w = tid >> 5, lane = tid & 31;
#pragma unroll
        for (int j = 0; j < 7; j++) {
            int i = w + 8*j;
            float mx = -1e30f;
            for (int m = lane; m < NPIX; m += 32) mx = fmaxf(mx, S[i*SSTR + m]);
#pragma unroll
            for (int off = 16; off > 0; off >>= 1)
                mx = fmaxf(mx, __shfl_xor_sync(0xffffffffu, mx, off));
            float sum = 0.f;
            for (int m = lane; m < NPIX; m += 32) {
                float e = __expf(S[i*SSTR + m] - mx);
                S[i*SSTR + m] = e;
                sum += e;
            }
#pragma unroll
            for (int off = 16; off > 0; off >>= 1)
                sum += __shfl_xor_sync(0xffffffffu, sum, off);
            if (lane == 0) rinv[i] = 1.0f / sum;
        }
    }

    // ---- phase B: O = P V ----
    float ob[12];
#pragma unroll
    for (int d = 0; d < 12; d++) ob[d] = 0.f;
    int i  = tid % TQ;
    int dg = tid / TQ;            // 0..3 valid
    bool active = tid < 4*TQ;     // 224 threads

    for (int n0 = 0; n0 < NPIX; n0 += TKK) {
        int cols = min(TKK, NPIX - n0);
        __syncthreads();
        for (int idx = tid; idx < TKK*12; idx += 256) {
            int mm = idx / 12, d4 = (idx % 12) * 4;
            if (mm < cols) {
                float4 vv = *(const float4*)&Vt[((size_t)(b*NPIX + n0 + mm))*C_DIM + h*HDIM + d4];
                *(float4*)&KV[mm*VS_STRIDE + d4] = vv;
            }
        }
        __syncthreads();
        if (active) {
            for (int mm = 0; mm < cols; mm += 4) {
                float4 p = *(const float4*)&S[i*SSTR + n0 + mm];
                float pv[4] = {p.x, p.y, p.z, p.w};
#pragma unroll
                for (int u = 0; u < 4; u++) {
                    const float* vrow = &KV[(mm + u)*VS_STRIDE + dg*12];
#pragma unroll
                    for (int d = 0; d < 12; d++) ob[d] += pv[u] * vrow[d];
                }
            }
        }
    }

    if (active) {
        float inv = rinv[i];
        size_t base = ((size_t)(b*NPIX + q0 + i))*C_DIM + h*HDIM + dg*12;
#pragma unroll
        for (int d = 0; d < 12; d++) {
            float v = ob[d] * inv;
            bf16 hi, lo; split_bf16(v, hi, lo);
            AOh[base + d] = hi; AOl[base + d] = lo;
        }
    }
}

// ---------------- host ----------------
extern "C" void kernel_launch(void* const* d_in, const int* in_sizes, int n_in,
                              void* d_out, int out_size)
{
    const float* x       = (const float*)d_in[0];
    const float* local_w = (const float*)d_in[1];
    const float* local_b = (const float*)d_in[2];
    const float* bn1_g   = (const float*)d_in[3];
    const float* bn1_b   = (const float*)d_in[4];
    const float* bn1_m   = (const float*)d_in[5];
    const float* bn1_v   = (const float*)d_in[6];
    const float* q_w     = (const float*)d_in[7];
    const float* q_b     = (const float*)d_in[8];
    const float* k_w     = (const float*)d_in[9];
    const float* k_b     = (const float*)d_in[10];
    const float* v_w     = (const float*)d_in[11];
    const float* v_b     = (const float*)d_in[12];
    const float* proj_w  = (const float*)d_in[13];
    const float* proj_b  = (const float*)d_in[14];
    const float* ffn1_w  = (const float*)d_in[15];
    const float* ffn1_b  = (const float*)d_in[16];
    const float* ffn2_w  = (const float*)d_in[17];
    const float* ffn2_b  = (const float*)d_in[18];
    const float* bn2_g   = (const float*)d_in[19];
    const float* bn2_b   = (const float*)d_in[20];
    const float* bn2_m   = (const float*)d_in[21];
    const float* bn2_v   = (const float*)d_in[22];

    float *q, *k, *v, *lx, *r;
    bf16 *lxh, *lxl, *aoh, *aol, *hh, *hl, *f1h, *f1l;
    bf16 *qwh, *qwl, *kwh, *kwl, *vwh, *vwl, *pwh, *pwl, *w1h, *w1l, *w2h, *w2l;
    cudaGetSymbolAddress((void**)&lx,  g_lx);
    cudaGetSymbolAddress((void**)&lxh, g_lxh);
    cudaGetSymbolAddress((void**)&lxl, g_lxl);
    cudaGetSymbolAddress((void**)&q,   g_q);
    cudaGetSymbolAddress((void**)&k,   g_k);
    cudaGetSymbolAddress((void**)&v,   g_v);
    cudaGetSymbolAddress((void**)&aoh, g_aoh);
    cudaGetSymbolAddress((void**)&aol, g_aol);
    cudaGetSymbolAddress((void**)&r,   g_r);
    cudaGetSymbolAddress((void**)&hh,  g_hh);
    cudaGetSymbolAddress((void**)&hl,  g_hl);
    cudaGetSymbolAddress((void**)&f1h, g_f1h);
    cudaGetSymbolAddress((void**)&f1l, g_f1l);
    cudaGetSymbolAddress((void**)&qwh, g_qwh); cudaGetSymbolAddress((void**)&qwl, g_qwl);
    cudaGetSymbolAddress((void**)&kwh, g_kwh); cudaGetSymbolAddress((void**)&kwl, g_kwl);
    cudaGetSymbolAddress((void**)&vwh, g_vwh); cudaGetSymbolAddress((void**)&vwl, g_vwl);
    cudaGetSymbolAddress((void**)&pwh, g_pwh); cudaGetSymbolAddress((void**)&pwl, g_pwl);
    cudaGetSymbolAddress((void**)&w1h, g_w1h); cudaGetSymbolAddress((void**)&w1l, g_w1l);
    cudaGetSymbolAddress((void**)&w2h, g_w2h); cudaGetSymbolAddress((void**)&w2l, g_w2l);

    cudaFuncSetAttribute(gemm_mma<0>, cudaFuncAttributeMaxDynamicSharedMemorySize, GEMM_SMEM);
    cudaFuncSetAttribute(gemm_mma<1>, cudaFuncAttributeMaxDynamicSharedMemorySize, GEMM_SMEM);
    cudaFuncSetAttribute(gemm_mma<2>, cudaFuncAttributeMaxDynamicSharedMemorySize, GEMM_SMEM);
    cudaFuncSetAttribute(gemm_mma<3>, cudaFuncAttributeMaxDynamicSharedMemorySize, GEMM_SMEM);
    cudaFuncSetAttribute(attn_kernel, cudaFuncAttributeMaxDynamicSharedMemorySize, ATTN_SMEM_BYTES);

    // 0. weight conversions (f32 -> bf16 hi/lo)
    const int nw = C_DIM*C_DIM, nf = FFN_DIM*C_DIM;
    cvt_kernel<<<(nw+255)/256, 256>>>(q_w,    qwh, qwl, nw);
    cvt_kernel<<<(nw+255)/256, 256>>>(k_w,    kwh, kwl, nw);
    cvt_kernel<<<(nw+255)/256, 256>>>(v_w,    vwh, vwl, nw);
    cvt_kernel<<<(nw+255)/256, 256>>>(proj_w, pwh, pwl, nw);
    cvt_kernel<<<(nf+255)/256, 256>>>(ffn1_w, w1h, w1l, nf);
    cvt_kernel<<<(nf+255)/256, 256>>>(ffn2_w, w2h, w2l, nf);

    // 1. depthwise conv + BN1
    dwconv_bn_kernel<<<(BATCH*C_DIM*NPIX + 255)/256, 256>>>(
        x, local_w, local_b, bn1_g, bn1_b, bn1_m, bn1_v);

    // 2. NCHW -> token-major (+ bf16 split)
    to_tokens_kernel<<<dim3(25, 12, BATCH), dim3(32, 8)>>>();

    dim3 g384(3, 98), g1536(12, 98);

    // 3. QKV (tensor cores via mma.sync, f32 outputs for fp32 attention)
    gemm_mma<0><<<g384, 256, GEMM_SMEM>>>(lxh, lxl, qwh, qwl, q_b, nullptr,
        nullptr, nullptr, nullptr, nullptr, q, nullptr, nullptr, C_DIM, C_DIM);
    gemm_mma<0><<<g384, 256, GEMM_SMEM>>>(lxh, lxl, kwh, kwl, k_b, nullptr,
        nullptr, nullptr, nullptr, nullptr, k, nullptr, nullptr, C_DIM, C_DIM);
    gemm_mma<0><<<g384, 256, GEMM_SMEM>>>(lxh, lxl, vwh, vwl, v_b, nullptr,
        nullptr, nullptr, nullptr, nullptr, v, nullptr, nullptr, C_DIM, C_DIM);

    // 4. attention (fp32; emits ao as bf16 hi/lo)
    attn_kernel<<<dim3(NPIX/TQ, HEADS, BATCH), 256, ATTN_SMEM_BYTES>>>(q, k, v, aoh, aol);

    // 5. proj + residual(lx) -> r (f32); BN2 -> h (hi/lo)
    gemm_mma<1><<<g384, 256, GEMM_SMEM>>>(aoh, aol, pwh, pwl, proj_b, lx,
        bn2_g, bn2_b, bn2_m, bn2_v, r, hh, hl, C_DIM, C_DIM);

    // 6. FFN1 + gelu -> f1 (hi/lo)
    gemm_mma<2><<<g1536, 256, GEMM_SMEM>>>(hh, hl, w1h, w1l, ffn1_b, nullptr,
        nullptr, nullptr, nullptr, nullptr, nullptr, f1h, f1l, C_DIM, FFN_DIM);

    // 7. FFN2 + residual(r), NCHW output
    gemm_mma<3><<<g384, 256, GEMM_SMEM>>>(f1h, f1l, w2h, w2l, ffn2_b, r,
        nullptr, nullptr, nullptr, nullptr, (float*)d_out, nullptr, nullptr, FFN_DIM, C_DIM);
}

// round 8
// speedup vs baseline: 3.0514x; 2.0192x over previous
#include <cuda_runtime.h>
#include <cuda_bf16.h>
#include <math.h>
#include <stdint.h>

typedef __nv_bfloat16 bf16;

#define BATCH   16
#define C_DIM   384
#define NPIX    784
#define T_TOK   (BATCH*NPIX)      // 12544
#define HEADS   8
#define HDIM    48
#define FFN_DIM 1536
#define BN_EPS  1e-5f

// ---------------- scratch (static device globals; no allocation) ----------------
__device__ float g_tmp[BATCH*C_DIM*NPIX];   // conv output, NCHW
__device__ float g_lx [T_TOK*C_DIM];        // token-major f32 (residual for proj)
__device__ bf16  g_lxh[T_TOK*C_DIM];
__device__ bf16  g_lxl[T_TOK*C_DIM];
__device__ bf16  g_qh [T_TOK*C_DIM];        // Q (scale folded) hi/lo, [t][c]
__device__ bf16  g_ql [T_TOK*C_DIM];
__device__ bf16  g_kh [T_TOK*C_DIM];        // K hi/lo, [t][c]
__device__ bf16  g_kl [T_TOK*C_DIM];
__device__ bf16  g_vth[T_TOK*C_DIM + 64];   // V^T hi/lo, [b][h][d][n] (+pad for tail overread)
__device__ bf16  g_vtl[T_TOK*C_DIM + 64];
__device__ bf16  g_aoh[T_TOK*C_DIM];        // attention out hi/lo
__device__ bf16  g_aol[T_TOK*C_DIM];
__device__ float g_r  [T_TOK*C_DIM];        // residual (proj + lx), f32
__device__ bf16  g_hh [T_TOK*C_DIM];        // bn2(residual) hi/lo
__device__ bf16  g_hl [T_TOK*C_DIM];
__device__ bf16  g_f1h[T_TOK*FFN_DIM];      // ffn1 output hi/lo
__device__ bf16  g_f1l[T_TOK*FFN_DIM];
// weights hi/lo
__device__ bf16  g_qwh[C_DIM*C_DIM], g_qwl[C_DIM*C_DIM];
__device__ bf16  g_kwh[C_DIM*C_DIM], g_kwl[C_DIM*C_DIM];
__device__ bf16  g_vwh[C_DIM*C_DIM], g_vwl[C_DIM*C_DIM];
__device__ bf16  g_pwh[C_DIM*C_DIM], g_pwl[C_DIM*C_DIM];
__device__ bf16  g_w1h[FFN_DIM*C_DIM], g_w1l[FFN_DIM*C_DIM];
__device__ bf16  g_w2h[C_DIM*FFN_DIM], g_w2l[C_DIM*FFN_DIM];

// ======================= helpers =======================
__device__ __forceinline__ uint32_t smem_u32(const void* p) {
    return (uint32_t)__cvta_generic_to_shared(p);
}
__device__ __forceinline__ void split_bf16(float x, bf16& hi, bf16& lo) {
    hi = __float2bfloat16_rn(x);
    lo = __float2bfloat16_rn(x - __bfloat162float(hi));
}
__device__ __forceinline__ uint32_t pack_bf2(bf16 a, bf16 b) {
    __nv_bfloat162 t; t.x = a; t.y = b;
    return *reinterpret_cast<uint32_t*>(&t);
}
__device__ __forceinline__ void ldsm4(uint32_t* r, uint32_t addr) {
    asm volatile("ldmatrix.sync.aligned.m8n8.x4.shared.b16 {%0,%1,%2,%3}, [%4];"
                 : "=r"(r[0]), "=r"(r[1]), "=r"(r[2]), "=r"(r[3]) : "r"(addr));
}
__device__ __forceinline__ void mma16816(float* c, const uint32_t* a, uint32_t b0, uint32_t b1) {
    asm volatile("mma.sync.aligned.m16n8k16.row.col.f32.bf16.bf16.f32 "
                 "{%0,%1,%2,%3}, {%4,%5,%6,%7}, {%8,%9}, {%0,%1,%2,%3};"
                 : "+f"(c[0]), "+f"(c[1]), "+f"(c[2]), "+f"(c[3])
                 : "r"(a[0]), "r"(a[1]), "r"(a[2]), "r"(a[3]), "r"(b0), "r"(b1));
}

// ---------------- f32 -> bf16 hi/lo conversion (weights) ----------------
__global__ void cvt_kernel(const float* __restrict__ src, bf16* __restrict__ h,
                           bf16* __restrict__ l, int n)
{
    int i = blockIdx.x * 256 + threadIdx.x;
    if (i < n) { bf16 hi, lo; split_bf16(src[i], hi, lo); h[i] = hi; l[i] = lo; }
}

// ---------------- depthwise 3x3 conv + BN1 (NCHW -> NCHW tmp) ----------------
__global__ void dwconv_bn_kernel(const float* __restrict__ x,
                                 const float* __restrict__ w,
                                 const float* __restrict__ bconv,
                                 const float* __restrict__ bg,
                                 const float* __restrict__ bb,
                                 const float* __restrict__ bm,
                                 const float* __restrict__ bv)
{
    int gid = blockIdx.x * blockDim.x + threadIdx.x;
    if (gid >= BATCH*C_DIM*NPIX) return;
    int hw = gid % NPIX;
    int bc = gid / NPIX;
    int c  = bc % C_DIM;
    int yy = hw / 28, xx = hw % 28;
    const float* xp = x + (size_t)bc * NPIX;
    const float* wp = w + c * 9;
    float s = 0.f;
#pragma unroll
    for (int ky = 0; ky < 3; ky++) {
        int y = yy + ky - 1;
        if ((unsigned)y < 28u) {
#pragma unroll
            for (int kx = 0; kx < 3; kx++) {
                int x2 = xx + kx - 1;
                if ((unsigned)x2 < 28u) s += wp[ky*3+kx] * xp[y*28 + x2];
            }
        }
    }
    s += bconv[c];
    float inv = rsqrtf(bv[c] + BN_EPS);
    g_tmp[gid] = (s - bm[c]) * inv * bg[c] + bb[c];
}

// ---------------- transpose NCHW -> token-major [t][c] (+ bf16 hi/lo) ----------------
__global__ void to_tokens_kernel()
{
    __shared__ float tile[32][33];
    int b   = blockIdx.z;
    int hw0 = blockIdx.x * 32;
    int c0  = blockIdx.y * 32;
    int tx = threadIdx.x, ty = threadIdx.y;   // 32 x 8
#pragma unroll
    for (int j = 0; j < 32; j += 8) {
        int c = c0 + ty + j, hw = hw0 + tx;
        tile[ty + j][tx] = (hw < NPIX) ? g_tmp[((size_t)b*C_DIM + c)*NPIX + hw] : 0.f;
    }
    __syncthreads();
#pragma unroll
    for (int j = 0; j < 32; j += 8) {
        int hw = hw0 + ty + j, c = c0 + tx;
        if (hw < NPIX) {
            float v = tile[tx][ty + j];
            size_t idx = ((size_t)b*NPIX + hw)*C_DIM + c;
            g_lx[idx] = v;
            bf16 hi, lo; split_bf16(v, hi, lo);
            g_lxh[idx] = hi; g_lxl[idx] = lo;
        }
    }
}

// ======================= mma.sync split-bf16 GEMM =======================
// D[t][o] = sum_k A[t][k]*W[o][k], A=Ah+Al, W=Wh+Wl (3 MMAs: hh, hl, lh)
// CTA tile 128x128, 8 warps in 4(m) x 2(n), warp tile 32x64, K chunk 64.
// MODE 0: (val)*mult -> bf16 hi/lo [t][N]       (Q with scale / K)
// MODE 1: +bias+res -> f32 out(r); BN2 -> hi/lo (proj)
// MODE 2: gelu(+bias) -> hi/lo                  (ffn1)
// MODE 3: +bias+res -> NCHW f32                 (ffn2 final)
// MODE 4: val -> bf16 hi/lo, head-transposed [b][h][d][n]  (V)
#define KC    64
#define ASTR  72                             // bf16 row stride (144B) - ldmatrix conflict-free
#define TILE_ELE (128*ASTR)
#define GEMM_SMEM (4*TILE_ELE*2)             // 73728 B

__device__ __forceinline__ void load_tile(const bf16* __restrict__ src, int rbase, int K, int k0,
                                          bf16* __restrict__ dst)
{
    int tid = threadIdx.x;
#pragma unroll
    for (int i = 0; i < 4; ++i) {
        int ch = tid + i*256;             // 0..1023
        int r = ch >> 3, c = ch & 7;
        uint4 v = *(const uint4*)(src + (size_t)(rbase + r)*K + k0 + c*8);
        *(uint4*)(dst + r*ASTR + c*8) = v;
    }
}

template<int MODE>
__global__ void __launch_bounds__(256, 2)
gemm_mma(const bf16* __restrict__ Ah, const bf16* __restrict__ Al,
         const bf16* __restrict__ Wh, const bf16* __restrict__ Wl,
         const float* __restrict__ bias, const float* __restrict__ res,
         const float* __restrict__ bng, const float* __restrict__ bnb,
         const float* __restrict__ bnm, const float* __restrict__ bnv,
         float* __restrict__ outf, bf16* __restrict__ oh, bf16* __restrict__ ol,
         int K, int N, float mult)
{
    extern __shared__ __align__(16) bf16 smb[];
    bf16* sAh = smb;
    bf16* sAl = smb + TILE_ELE;
    bf16* sWh = smb + 2*TILE_ELE;
    bf16* sWl = smb + 3*TILE_ELE;

    const int tid = threadIdx.x;
    const int wid = tid >> 5, l = tid & 31;
    const int wm = wid & 3, wn = wid >> 2;    // warp tile: rows wm*32, cols wn*64
    const int t0 = blockIdx.y * 128;
    const int o0 = blockIdx.x * 128;

    float acc[2][8][4];
#pragma unroll
    for (int f = 0; f < 2; f++)
#pragma unroll
        for (int g = 0; g < 8; g++)
#pragma unroll
            for (int i = 0; i < 4; i++) acc[f][g][i] = 0.f;

    const int arow = l & 15;
    const int acol = (l >> 4) * 8;
    const int brow = ((l >> 4) << 3) + (l & 7);
    const int bcol = ((l >> 3) & 1) * 8;
    const uint32_t baseAh = smem_u32(sAh), baseAl = smem_u32(sAl);
    const uint32_t baseWh = smem_u32(sWh), baseWl = smem_u32(sWl);

    const int nch = K / KC;
    for (int ch = 0; ch < nch; ++ch) {
        __syncthreads();
        const int k0g = ch * KC;
        load_tile(Ah, t0, K, k0g, sAh);
        load_tile(Al, t0, K, k0g, sAl);
        load_tile(Wh, o0, K, k0g, sWh);
        load_tile(Wl, o0, K, k0g, sWl);
        __syncthreads();

#pragma unroll
        for (int kk = 0; kk < 4; ++kk) {
            const int k0 = kk * 16;
            uint32_t ah[2][4], al2[2][4];
#pragma unroll
            for (int f = 0; f < 2; ++f) {
                uint32_t off = (uint32_t)(((wm*32 + f*16 + arow)*ASTR + k0 + acol) * 2);
                ldsm4(ah[f],  baseAh + off);
                ldsm4(al2[f], baseAl + off);
            }
#pragma unroll
            for (int gp = 0; gp < 4; ++gp) {
                uint32_t bh[4], bl[4];
                uint32_t off = (uint32_t)(((wn*64 + gp*16 + brow)*ASTR + k0 + bcol) * 2);
                ldsm4(bh, baseWh + off);
                ldsm4(bl, baseWl + off);
#pragma unroll
                for (int f = 0; f < 2; ++f) {
                    mma16816(acc[f][2*gp],   ah[f],  bh[0], bh[1]);
                    mma16816(acc[f][2*gp+1], ah[f],  bh[2], bh[3]);
                    mma16816(acc[f][2*gp],   ah[f],  bl[0], bl[1]);
                    mma16816(acc[f][2*gp+1], ah[f],  bl[2], bl[3]);
                    mma16816(acc[f][2*gp],   al2[f], bh[0], bh[1]);
                    mma16816(acc[f][2*gp+1], al2[f], bh[2], bh[3]);
                }
            }
        }
    }

    // ---- epilogue ----
    const int row_in = l >> 2, col_in = (l & 3) * 2;
#pragma unroll
    for (int f = 0; f < 2; ++f) {
        const int tb = t0 + wm*32 + f*16 + row_in;
#pragma unroll
        for (int g = 0; g < 8; ++g) {
            const int o = o0 + wn*64 + g*8 + col_in;
#pragma unroll
            for (int hhalf = 0; hhalf < 2; ++hhalf) {
                const int t = tb + hhalf*8;
                const float c0 = acc[f][g][hhalf*2 + 0];
                const float c1 = acc[f][g][hhalf*2 + 1];
                if (MODE == 0) {
                    float v0 = (c0 + bias[o]) * mult;
                    float v1 = (c1 + bias[o+1]) * mult;
                    bf16 h0, l0_, h1, l1_;
                    split_bf16(v0, h0, l0_); split_bf16(v1, h1, l1_);
                    *(uint32_t*)&oh[(size_t)t*N + o] = pack_bf2(h0, h1);
                    *(uint32_t*)&ol[(size_t)t*N + o] = pack_bf2(l0_, l1_);
                } else if (MODE == 1) {
#pragma unroll
                    for (int u = 0; u < 2; ++u) {
                        int oo = o + u;
                        size_t idx = (size_t)t*C_DIM + oo;
                        float val = (u ? c1 : c0) + bias[oo] + res[idx];
                        outf[idx] = val;
                        float inv = rsqrtf(bnv[oo] + BN_EPS);
                        float hb = (val - bnm[oo]) * inv * bng[oo] + bnb[oo];
                        bf16 hi, lo; split_bf16(hb, hi, lo);
                        oh[idx] = hi; ol[idx] = lo;
                    }
                } else if (MODE == 2) {
#pragma unroll
                    for (int u = 0; u < 2; ++u) {
                        int oo = o + u;
                        float val = (u ? c1 : c0) + bias[oo];
                        float ge = 0.5f * val * (1.0f + erff(val * 0.7071067811865475f));
                        size_t idx = (size_t)t*N + oo;
                        bf16 hi, lo; split_bf16(ge, hi, lo);
                        oh[idx] = hi; ol[idx] = lo;
                    }
                } else if (MODE == 3) { // NCHW final
                    const int bb2 = t / NPIX;
                    const int nn  = t - bb2 * NPIX;
#pragma unroll
                    for (int u = 0; u < 2; ++u) {
                        int oo = o + u;
                        float val = (u ? c1 : c0) + bias[oo] + res[(size_t)t*C_DIM + oo];
                        outf[((size_t)bb2*C_DIM + oo)*NPIX + nn] = val;
                    }
                } else { // MODE 4: V head-transposed [b][h][d][n]
                    const int bb2 = t / NPIX;
                    const int nn  = t - bb2 * NPIX;
#pragma unroll
                    for (int u = 0; u < 2; ++u) {
                        int oo = o + u;
                        int hh2 = oo / HDIM, dd = oo - hh2*HDIM;
                        float val = (u ? c1 : c0) + bias[oo];
                        bf16 hi, lo; split_bf16(val, hi, lo);
                        size_t dst = ((size_t)((bb2*HEADS + hh2)*HDIM + dd))*NPIX + nn;
                        oh[dst] = hi; ol[dst] = lo;
                    }
                }
            }
        }
    }
}

// ======================= flash-style mma attention =======================
// CTA: (qb, h, b), 8 warps x 16 query rows = 128 queries; keys streamed 64-wide.
// All operands split-bf16, 3-MMA products. Online softmax in registers.
#define AQ_STR 56
#define AK_STR 56
#define AV_STR 72
#define ATTN_SMEM ((2*128*AQ_STR + 2*64*AK_STR + 2*48*AV_STR) * 2)   // 56832 B

__global__ void __launch_bounds__(256)
attn_mma(const bf16* __restrict__ Qh, const bf16* __restrict__ Ql,
         const bf16* __restrict__ Kh, const bf16* __restrict__ Kl,
         const bf16* __restrict__ Vth, const bf16* __restrict__ Vtl,
         bf16* __restrict__ AOh, bf16* __restrict__ AOl)
{
    extern __shared__ __align__(16) bf16 sm_[];
    bf16* sQh = sm_;
    bf16* sQl = sQh + 128*AQ_STR;
    bf16* sKh = sQl + 128*AQ_STR;
    bf16* sKl = sKh + 64*AK_STR;
    bf16* sVh = sKl + 64*AK_STR;
    bf16* sVl = sVh + 48*AV_STR;

    const int tid = threadIdx.x, w = tid >> 5, ln = tid & 31;
    const int qb = blockIdx.x, h = blockIdx.y, b = blockIdx.z;
    const int q0 = qb * 128;

    // ---- load Q tile (rows clamped to image) ----
    for (int idx = tid; idx < 128*6; idx += 256) {
        int r = idx / 6, cs = idx % 6;
        int t = b*NPIX + min(q0 + r, NPIX - 1);
        const bf16* ph_ = Qh + (size_t)t*C_DIM + h*HDIM;
        const bf16* pl_ = Ql + (size_t)t*C_DIM + h*HDIM;
        *(uint4*)(sQh + r*AQ_STR + cs*8) = *((const uint4*)ph_ + cs);
        *(uint4*)(sQl + r*AQ_STR + cs*8) = *((const uint4*)pl_ + cs);
    }
    __syncthreads();

    // ---- Q fragments (persistent) ----
    const int arow = ln & 15, acol = (ln >> 4) * 8;
    const int brow = ((ln >> 4) << 3) + (ln & 7), bcol = ((ln >> 3) & 1) * 8;
    uint32_t qfh[3][4], qfl[3][4];
    {
        const uint32_t qb_h = smem_u32(sQh), qb_l = smem_u32(sQl);
#pragma unroll
        for (int kc = 0; kc < 3; kc++) {
            uint32_t off = (uint32_t)(((w*16 + arow)*AQ_STR + kc*16 + acol) * 2);
            ldsm4(qfh[kc], qb_h + off);
            ldsm4(qfl[kc], qb_l + off);
        }
    }

    const uint32_t kb_h = smem_u32(sKh), kb_l = smem_u32(sKl);
    const uint32_t vb_h = smem_u32(sVh), vb_l = smem_u32(sVl);

    float rm0 = -1e30f, rm1 = -1e30f;   // running max (rows ln/4, ln/4+8)
    float rl0 = 0.f,    rl1 = 0.f;      // running sum
    float O[6][4];
#pragma unroll
    for (int j = 0; j < 6; j++)
#pragma unroll
        for (int i = 0; i < 4; i++) O[j][i] = 0.f;

    for (int n0 = 0; n0 < NPIX; n0 += 64) {
        __syncthreads();
        // load K block [64][48] hi/lo
        for (int idx = tid; idx < 64*6; idx += 256) {
            int r = idx / 6, cs = idx % 6;
            int t = b*NPIX + min(n0 + r, NPIX - 1);
            *(uint4*)(sKh + r*AK_STR + cs*8) = *((const uint4*)(Kh + (size_t)t*C_DIM + h*HDIM) + cs);
            *(uint4*)(sKl + r*AK_STR + cs*8) = *((const uint4*)(Kl + (size_t)t*C_DIM + h*HDIM) + cs);
        }
        // load V^T block [48][64] hi/lo
        for (int idx = tid; idx < 48*8; idx += 256) {
            int r = idx / 8, cs = idx % 8;
            size_t base = ((size_t)((b*HEADS + h)*HDIM + r))*NPIX + n0;
            *(uint4*)(sVh + r*AV_STR + cs*8) = *((const uint4*)(Vth + base) + cs);
            *(uint4*)(sVl + r*AV_STR + cs*8) = *((const uint4*)(Vtl + base) + cs);
        }
        __syncthreads();

        // ---- S = Q K^T (8 n-tiles of 8 keys) ----
        float s[8][4];
#pragma unroll
        for (int j = 0; j < 8; j++)
#pragma unroll
            for (int i = 0; i < 4; i++) s[j][i] = 0.f;

#pragma unroll
        for (int kc = 0; kc < 3; kc++) {
#pragma unroll
            for (int g = 0; g < 4; g++) {
                uint32_t off = (uint32_t)(((g*16 + brow)*AK_STR + kc*16 + bcol) * 2);
                uint32_t kh4[4], kl4[4];
                ldsm4(kh4, kb_h + off);
                ldsm4(kl4, kb_l + off);
                mma16816(s[2*g],   qfh[kc], kh4[0], kh4[1]);
                mma16816(s[2*g+1], qfh[kc], kh4[2], kh4[3]);
                mma16816(s[2*g],   qfh[kc], kl4[0], kl4[1]);
                mma16816(s[2*g+1], qfh[kc], kl4[2], kl4[3]);
                mma16816(s[2*g],   qfl[kc], kh4[0], kh4[1]);
                mma16816(s[2*g+1], qfl[kc], kh4[2], kh4[3]);
            }
        }

        // ---- mask tail keys ----
        if (n0 + 64 > NPIX) {
            int c2 = 2*(ln & 3);
#pragma unroll
            for (int j = 0; j < 8; j++) {
                int col = n0 + 8*j + c2;
                if (col >= NPIX) { s[j][0] = s[j][1] = s[j][2] = s[j][3] = -1e30f; }
            }
        }

        // ---- online softmax ----
        float bm0 = -1e30f, bm1 = -1e30f;
#pragma unroll
        for (int j = 0; j < 8; j++) {
            bm0 = fmaxf(bm0, fmaxf(s[j][0], s[j][1]));
            bm1 = fmaxf(bm1, fmaxf(s[j][2], s[j][3]));
        }
        bm0 = fmaxf(bm0, __shfl_xor_sync(0xffffffffu, bm0, 1));
        bm0 = fmaxf(bm0, __shfl_xor_sync(0xffffffffu, bm0, 2));
        bm1 = fmaxf(bm1, __shfl_xor_sync(0xffffffffu, bm1, 1));
        bm1 = fmaxf(bm1, __shfl_xor_sync(0xffffffffu, bm1, 2));
        float nm0 = fmaxf(rm0, bm0), nm1 = fmaxf(rm1, bm1);
        float sc0 = __expf(rm0 - nm0), sc1 = __expf(rm1 - nm1);
        rm0 = nm0; rm1 = nm1;
        float bs0 = 0.f, bs1 = 0.f;
#pragma unroll
        for (int j = 0; j < 8; j++) {
            s[j][0] = __expf(s[j][0] - nm0);
            s[j][1] = __expf(s[j][1] - nm0);
            s[j][2] = __expf(s[j][2] - nm1);
            s[j][3] = __expf(s[j][3] - nm1);
            bs0 += s[j][0] + s[j][1];
            bs1 += s[j][2] + s[j][3];
        }
        bs0 += __shfl_xor_sync(0xffffffffu, bs0, 1);
        bs0 += __shfl_xor_sync(0xffffffffu, bs0, 2);
        bs1 += __shfl_xor_sync(0xffffffffu, bs1, 1);
        bs1 += __shfl_xor_sync(0xffffffffu, bs1, 2);
        rl0 = rl0*sc0 + bs0;
        rl1 = rl1*sc1 + bs1;
#pragma unroll
        for (int j = 0; j < 6; j++) {
            O[j][0] *= sc0; O[j][1] *= sc0;
            O[j][2] *= sc1; O[j][3] *= sc1;
        }

        // ---- O += P V (P fragments re-packed from S regs, split hi/lo) ----
#pragma unroll
        for (int kc = 0; kc < 4; kc++) {
            uint32_t ph[4], pl[4];
            {
                bf16 h0, l0_, h1, l1_;
                split_bf16(s[2*kc][0], h0, l0_); split_bf16(s[2*kc][1], h1, l1_);
                ph[0] = pack_bf2(h0, h1); pl[0] = pack_bf2(l0_, l1_);
                split_bf16(s[2*kc][2], h0, l0_); split_bf16(s[2*kc][3], h1, l1_);
                ph[1] = pack_bf2(h0, h1); pl[1] = pack_bf2(l0_, l1_);
                split_bf16(s[2*kc+1][0], h0, l0_); split_bf16(s[2*kc+1][1], h1, l1_);
                ph[2] = pack_bf2(h0, h1); pl[2] = pack_bf2(l0_, l1_);
                split_bf16(s[2*kc+1][2], h0, l0_); split_bf16(s[2*kc+1][3], h1, l1_);
                ph[3] = pack_bf2(h0, h1); pl[3] = pack_bf2(l0_, l1_);
            }
#pragma unroll
            for (int dg = 0; dg < 3; dg++) {
                uint32_t off = (uint32_t)(((dg*16 + brow)*AV_STR + kc*16 + bcol) * 2);
                uint32_t vh4[4], vl4[4];
                ldsm4(vh4, vb_h + off);
                ldsm4(vl4, vb_l + off);
                mma16816(O[2*dg],   ph, vh4[0], vh4[1]);
                mma16816(O[2*dg+1], ph, vh4[2], vh4[3]);
                mma16816(O[2*dg],   ph, vl4[0], vl4[1]);
                mma16816(O[2*dg+1], ph, vl4[2], vl4[3]);
                mma16816(O[2*dg],   pl, vh4[0], vh4[1]);
                mma16816(O[2*dg+1], pl, vh4[2], vh4[3]);
            }
        }
    }

    // ---- epilogue: normalize + split-store ----
    float inv0 = 1.f / rl0, inv1 = 1.f / rl1;
    int r0 = q0 + w*16 + (ln >> 2);
    int r1 = r0 + 8;
    int cbase = h*HDIM + 2*(ln & 3);
#pragma unroll
    for (int jn = 0; jn < 6; jn++) {
        int c = cbase + 8*jn;
        if (r0 < NPIX) {
            size_t idx = (size_t)(b*NPIX + r0)*C_DIM + c;
            bf16 h0, l0_, h1, l1_;
            split_bf16(O[jn][0]*inv0, h0, l0_);
            split_bf16(O[jn][1]*inv0, h1, l1_);
            *(uint32_t*)&AOh[idx] = pack_bf2(h0, h1);
            *(uint32_t*)&AOl[idx] = pack_bf2(l0_, l1_);
        }
        if (r1 < NPIX) {
            size_t idx = (size_t)(b*NPIX + r1)*C_DIM + c;
            bf16 h0, l0_, h1, l1_;
            split_bf16(O[jn][2]*inv1, h0, l0_);
            split_bf16(O[jn][3]*inv1, h1, l1_);
            *(uint32_t*)&AOh[idx] = pack_bf2(h0, h1);
            *(uint32_t*)&AOl[idx] = pack_bf2(l0_, l1_);
        }
    }
}

// ---------------- host ----------------
extern "C" void kernel_launch(void* const* d_in, const int* in_sizes, int n_in,
                              void* d_out, int out_size)
{
    const float* x       = (const float*)d_in[0];
    const float* local_w = (const float*)d_in[1];
    const float* local_b = (const float*)d_in[2];
    const float* bn1_g   = (const float*)d_in[3];
    const float* bn1_b   = (const float*)d_in[4];
    const float* bn1_m   = (const float*)d_in[5];
    const float* bn1_v   = (const float*)d_in[6];
    const float* q_w     = (const float*)d_in[7];
    const float* q_b     = (const float*)d_in[8];
    const float* k_w     = (const float*)d_in[9];
    const float* k_b     = (const float*)d_in[10];
    const float* v_w     = (const float*)d_in[11];
    const float* v_b     = (const float*)d_in[12];
    const float* proj_w  = (const float*)d_in[13];
    const float* proj_b  = (const float*)d_in[14];
    const float* ffn1_w  = (const float*)d_in[15];
    const float* ffn1_b  = (const float*)d_in[16];
    const float* ffn2_w  = (const float*)d_in[17];
    const float* ffn2_b  = (const float*)d_in[18];
    const float* bn2_g   = (const float*)d_in[19];
    const float* bn2_b   = (const float*)d_in[20];
    const float* bn2_m   = (const float*)d_in[21];
    const float* bn2_v   = (const float*)d_in[22];

    float *lx, *r;
    bf16 *lxh, *lxl, *qh, *ql, *kh, *kl, *vth, *vtl, *aoh, *aol, *hh, *hl, *f1h, *f1l;
    bf16 *qwh, *qwl, *kwh, *kwl, *vwh, *vwl, *pwh, *pwl, *w1h, *w1l, *w2h, *w2l;
    cudaGetSymbolAddress((void**)&lx,  g_lx);
    cudaGetSymbolAddress((void**)&lxh, g_lxh);
    cudaGetSymbolAddress((void**)&lxl, g_lxl);
    cudaGetSymbolAddress((void**)&qh,  g_qh);
    cudaGetSymbolAddress((void**)&ql,  g_ql);
    cudaGetSymbolAddress((void**)&kh,  g_kh);
    cudaGetSymbolAddress((void**)&kl,  g_kl);
    cudaGetSymbolAddress((void**)&vth, g_vth);
    cudaGetSymbolAddress((void**)&vtl, g_vtl);
    cudaGetSymbolAddress((void**)&aoh, g_aoh);
    cudaGetSymbolAddress((void**)&aol, g_aol);
    cudaGetSymbolAddress((void**)&r,   g_r);
    cudaGetSymbolAddress((void**)&hh,  g_hh);
    cudaGetSymbolAddress((void**)&hl,  g_hl);
    cudaGetSymbolAddress((void**)&f1h, g_f1h);
    cudaGetSymbolAddress((void**)&f1l, g_f1l);
    cudaGetSymbolAddress((void**)&qwh, g_qwh); cudaGetSymbolAddress((void**)&qwl, g_qwl);
    cudaGetSymbolAddress((void**)&kwh, g_kwh); cudaGetSymbolAddress((void**)&kwl, g_kwl);
    cudaGetSymbolAddress((void**)&vwh, g_vwh); cudaGetSymbolAddress((void**)&vwl, g_vwl);
    cudaGetSymbolAddress((void**)&pwh, g_pwh); cudaGetSymbolAddress((void**)&pwl, g_pwl);
    cudaGetSymbolAddress((void**)&w1h, g_w1h); cudaGetSymbolAddress((void**)&w1l, g_w1l);
    cudaGetSymbolAddress((void**)&w2h, g_w2h); cudaGetSymbolAddress((void**)&w2l, g_w2l);

    cudaFuncSetAttribute(gemm_mma<0>, cudaFuncAttributeMaxDynamicSharedMemorySize, GEMM_SMEM);
    cudaFuncSetAttribute(gemm_mma<1>, cudaFuncAttributeMaxDynamicSharedMemorySize, GEMM_SMEM);
    cudaFuncSetAttribute(gemm_mma<2>, cudaFuncAttributeMaxDynamicSharedMemorySize, GEMM_SMEM);
    cudaFuncSetAttribute(gemm_mma<3>, cudaFuncAttributeMaxDynamicSharedMemorySize, GEMM_SMEM);
    cudaFuncSetAttribute(gemm_mma<4>, cudaFuncAttributeMaxDynamicSharedMemorySize, GEMM_SMEM);
    cudaFuncSetAttribute(attn_mma,    cudaFuncAttributeMaxDynamicSharedMemorySize, ATTN_SMEM);

    // 0. weight conversions (f32 -> bf16 hi/lo)
    const int nw = C_DIM*C_DIM, nf = FFN_DIM*C_DIM;
    cvt_kernel<<<(nw+255)/256, 256>>>(q_w,    qwh, qwl, nw);
    cvt_kernel<<<(nw+255)/256, 256>>>(k_w,    kwh, kwl, nw);
    cvt_kernel<<<(nw+255)/256, 256>>>(v_w,    vwh, vwl, nw);
    cvt_kernel<<<(nw+255)/256, 256>>>(proj_w, pwh, pwl, nw);
    cvt_kernel<<<(nf+255)/256, 256>>>(ffn1_w, w1h, w1l, nf);
    cvt_kernel<<<(nf+255)/256, 256>>>(ffn2_w, w2h, w2l, nf);

    // 1. depthwise conv + BN1
    dwconv_bn_kernel<<<(BATCH*C_DIM*NPIX + 255)/256, 256>>>(
        x, local_w, local_b, bn1_g, bn1_b, bn1_m, bn1_v);

    // 2. NCHW -> token-major (+ bf16 split)
    to_tokens_kernel<<<dim3(25, 12, BATCH), dim3(32, 8)>>>();

    dim3 g384(3, 98), g1536(12, 98);
    const float scale = 0.14433756729740643f;   // 48^-0.5

    // 3. QKV: Q (scale folded) / K -> [t][c] hi/lo; V -> [b][h][d][n] hi/lo
    gemm_mma<0><<<g384, 256, GEMM_SMEM>>>(lxh, lxl, qwh, qwl, q_b, nullptr,
        nullptr, nullptr, nullptr, nullptr, nullptr, qh, ql, C_DIM, C_DIM, scale);
    gemm_mma<0><<<g384, 256, GEMM_SMEM>>>(lxh, lxl, kwh, kwl, k_b, nullptr,
        nullptr, nullptr, nullptr, nullptr, nullptr, kh, kl, C_DIM, C_DIM, 1.0f);
    gemm_mma<4><<<g384, 256, GEMM_SMEM>>>(lxh, lxl, vwh, vwl, v_b, nullptr,
        nullptr, nullptr, nullptr, nullptr, nullptr, vth, vtl, C_DIM, C_DIM, 1.0f);

    // 4. flash attention (tensor cores) -> ao hi/lo
    attn_mma<<<dim3(7, HEADS, BATCH), 256, ATTN_SMEM>>>(qh, ql, kh, kl, vth, vtl, aoh, aol);

    // 5. proj + residual(lx) -> r (f32); BN2 -> h (hi/lo)
    gemm_mma<1><<<g384, 256, GEMM_SMEM>>>(aoh, aol, pwh, pwl, proj_b, lx,
        bn2_g, bn2_b, bn2_m, bn2_v, r, hh, hl, C_DIM, C_DIM, 1.0f);

    // 6. FFN1 + gelu -> f1 (hi/lo)
    gemm_mma<2><<<g1536, 256, GEMM_SMEM>>>(hh, hl, w1h, w1l, ffn1_b, nullptr,
        nullptr, nullptr, nullptr, nullptr, nullptr, f1h, f1l, C_DIM, FFN_DIM, 1.0f);

    // 7. FFN2 + residual(r), NCHW output
    gemm_mma<3><<<g384, 256, GEMM_SMEM>>>(f1h, f1l, w2h, w2l, ffn2_b, r,
        nullptr, nullptr, nullptr, nullptr, (float*)d_out, nullptr, nullptr, FFN_DIM, C_DIM, 1.0f);
}

// round 9
// speedup vs baseline: 3.0913x; 1.0131x over previous
#include <cuda_runtime.h>
#include <cuda_bf16.h>
#include <math.h>
#include <stdint.h>

typedef __nv_bfloat16 bf16;

#define BATCH   16
#define C_DIM   384
#define NPIX    784
#define T_TOK   (BATCH*NPIX)      // 12544
#define HEADS   8
#define HDIM    48
#define FFN_DIM 1536
#define BN_EPS  1e-5f

// ---------------- scratch (static device globals; no allocation) ----------------
__device__ float g_lx [T_TOK*C_DIM];        // token-major f32 (residual for proj)
__device__ bf16  g_lxh[T_TOK*C_DIM];
__device__ bf16  g_lxl[T_TOK*C_DIM];
__device__ bf16  g_qh [T_TOK*C_DIM];        // Q (scale folded) hi/lo, [t][c]
__device__ bf16  g_ql [T_TOK*C_DIM];
__device__ bf16  g_kh [T_TOK*C_DIM];        // K hi/lo, [t][c]
__device__ bf16  g_kl [T_TOK*C_DIM];
__device__ bf16  g_vth[T_TOK*C_DIM + 64];   // V^T hi/lo, [b][h][d][n] (+pad for tail overread)
__device__ bf16  g_vtl[T_TOK*C_DIM + 64];
__device__ bf16  g_aoh[T_TOK*C_DIM];        // attention out hi/lo
__device__ bf16  g_aol[T_TOK*C_DIM];
__device__ float g_r  [T_TOK*C_DIM];        // residual (proj + lx), f32
__device__ bf16  g_hh [T_TOK*C_DIM];        // bn2(residual) hi/lo
__device__ bf16  g_hl [T_TOK*C_DIM];
__device__ bf16  g_f1h[T_TOK*FFN_DIM];      // ffn1 output hi/lo
__device__ bf16  g_f1l[T_TOK*FFN_DIM];
// weights hi/lo
__device__ bf16  g_qwh[C_DIM*C_DIM], g_qwl[C_DIM*C_DIM];
__device__ bf16  g_kwh[C_DIM*C_DIM], g_kwl[C_DIM*C_DIM];
__device__ bf16  g_vwh[C_DIM*C_DIM], g_vwl[C_DIM*C_DIM];
__device__ bf16  g_pwh[C_DIM*C_DIM], g_pwl[C_DIM*C_DIM];
__device__ bf16  g_w1h[FFN_DIM*C_DIM], g_w1l[FFN_DIM*C_DIM];
__device__ bf16  g_w2h[C_DIM*FFN_DIM], g_w2l[C_DIM*FFN_DIM];

// ======================= helpers =======================
__device__ __forceinline__ uint32_t smem_u32(const void* p) {
    return (uint32_t)__cvta_generic_to_shared(p);
}
__device__ __forceinline__ void split_bf16(float x, bf16& hi, bf16& lo) {
    hi = __float2bfloat16_rn(x);
    lo = __float2bfloat16_rn(x - __bfloat162float(hi));
}
__device__ __forceinline__ uint32_t pack_bf2(bf16 a, bf16 b) {
    __nv_bfloat162 t; t.x = a; t.y = b;
    return *reinterpret_cast<uint32_t*>(&t);
}
__device__ __forceinline__ void ldsm4(uint32_t* r, uint32_t addr) {
    asm volatile("ldmatrix.sync.aligned.m8n8.x4.shared.b16 {%0,%1,%2,%3}, [%4];"
                 : "=r"(r[0]), "=r"(r[1]), "=r"(r[2]), "=r"(r[3]) : "r"(addr));
}
__device__ __forceinline__ void mma16816(float* c, const uint32_t* a, uint32_t b0, uint32_t b1) {
    asm volatile("mma.sync.aligned.m16n8k16.row.col.f32.bf16.bf16.f32 "
                 "{%0,%1,%2,%3}, {%4,%5,%6,%7}, {%8,%9}, {%0,%1,%2,%3};"
                 : "+f"(c[0]), "+f"(c[1]), "+f"(c[2]), "+f"(c[3])
                 : "r"(a[0]), "r"(a[1]), "r"(a[2]), "r"(a[3]), "r"(b0), "r"(b1));
}
__device__ __forceinline__ void cp16(uint32_t dst, const void* src) {
    asm volatile("cp.async.cg.shared.global [%0], [%1], 16;" :: "r"(dst), "l"(src));
}
#define CP_COMMIT() asm volatile("cp.async.commit_group;")
#define CP_WAIT1()  asm volatile("cp.async.wait_group 1;")
#define CP_WAIT0()  asm volatile("cp.async.wait_group 0;")

// ---------------- merged f32 -> bf16 hi/lo conversion (all weights) ----------------
#define NW (C_DIM*C_DIM)       // 147456
#define NF (FFN_DIM*C_DIM)     // 589824
__global__ void cvt_all_kernel(
    const float* __restrict__ s0, bf16* __restrict__ h0, bf16* __restrict__ l0,
    const float* __restrict__ s1, bf16* __restrict__ h1, bf16* __restrict__ l1,
    const float* __restrict__ s2, bf16* __restrict__ h2, bf16* __restrict__ l2,
    const float* __restrict__ s3, bf16* __restrict__ h3, bf16* __restrict__ l3,
    const float* __restrict__ s4, bf16* __restrict__ h4, bf16* __restrict__ l4,
    const float* __restrict__ s5, bf16* __restrict__ h5, bf16* __restrict__ l5)
{
    int idx = blockIdx.x * 256 + threadIdx.x;
    const float* s; bf16 *h, *l; int off;
    if (idx < 4*NW) {
        int w = idx / NW; off = idx - w*NW;
        s = (w==0) ? s0 : (w==1) ? s1 : (w==2) ? s2 : s3;
        h = (w==0) ? h0 : (w==1) ? h1 : (w==2) ? h2 : h3;
        l = (w==0) ? l0 : (w==1) ? l1 : (w==2) ? l2 : l3;
    } else {
        int i2 = idx - 4*NW;
        if (i2 < NF)            { s = s4; h = h4; l = l4; off = i2; }
        else if (i2 < 2*NF)     { s = s5; h = h5; l = l5; off = i2 - NF; }
        else return;
    }
    bf16 hi, lo; split_bf16(s[off], hi, lo); h[off] = hi; l[off] = lo;
}

// ---------------- fused depthwise 3x3 conv + BN1 + transpose -> token-major ----------------
__global__ void conv_tokens_kernel(const float* __restrict__ x,
                                   const float* __restrict__ w,
                                   const float* __restrict__ bconv,
                                   const float* __restrict__ bg,
                                   const float* __restrict__ bb,
                                   const float* __restrict__ bm,
                                   const float* __restrict__ bv)
{
    __shared__ float tile[32][33];
    int b   = blockIdx.z;
    int hw0 = blockIdx.x * 32;
    int c0  = blockIdx.y * 32;
    int tx = threadIdx.x, ty = threadIdx.y;   // 32 x 8
#pragma unroll
    for (int j = 0; j < 32; j += 8) {
        int c = c0 + ty + j, hw = hw0 + tx;
        float val = 0.f;
        if (hw < NPIX) {
            int yy = hw / 28, xx = hw % 28;
            const float* xp = x + ((size_t)b*C_DIM + c) * NPIX;
            const float* wp = w + c * 9;
            float s = 0.f;
#pragma unroll
            for (int ky = 0; ky < 3; ky++) {
                int y = yy + ky - 1;
                if ((unsigned)y < 28u) {
#pragma unroll
                    for (int kx = 0; kx < 3; kx++) {
                        int x2 = xx + kx - 1;
                        if ((unsigned)x2 < 28u) s += wp[ky*3+kx] * xp[y*28 + x2];
                    }
                }
            }
            s += bconv[c];
            float inv = rsqrtf(bv[c] + BN_EPS);
            val = (s - bm[c]) * inv * bg[c] + bb[c];
        }
        tile[ty + j][tx] = val;
    }
    __syncthreads();
#pragma unroll
    for (int j = 0; j < 32; j += 8) {
        int hw = hw0 + ty + j, c = c0 + tx;
        if (hw < NPIX) {
            float v = tile[tx][ty + j];
            size_t idx = ((size_t)b*NPIX + hw)*C_DIM + c;
            g_lx[idx] = v;
            bf16 hi, lo; split_bf16(v, hi, lo);
            g_lxh[idx] = hi; g_lxl[idx] = lo;
        }
    }
}

// ======================= cp.async double-buffered split-bf16 GEMM =======================
// D[t][o] = sum_k A[t][k]*W[o][k], A=Ah+Al, W=Wh+Wl (3 MMAs: hh, hl, lh)
// CTA tile 128x128, 8 warps 4(m)x2(n), warp tile 32x64. K chunk 32, 2 stages.
#define KC    32
#define ASTR  40                             // bf16 row stride; (r*5 mod 8) hits all bank groups
#define TILE_ELE (128*ASTR)                  // 5120 elements
#define TILE_B   (TILE_ELE*2)                // 10240 B
#define STAGE_B  (4*TILE_B)                  // 40960 B
#define GEMM_SMEM (2*STAGE_B)                // 81920 B

__device__ __forceinline__ void gemm_load_stage(
    const bf16* __restrict__ Ah, const bf16* __restrict__ Al,
    const bf16* __restrict__ Wh, const bf16* __restrict__ Wl,
    int t0, int o0, int K, int k0, uint32_t su)
{
    int tid = threadIdx.x;
#pragma unroll
    for (int i = 0; i < 2; ++i) {
        int ch = tid + i*256;             // 0..511
        int r = ch >> 2, c = ch & 3;
        uint32_t d = (uint32_t)((r*ASTR + c*8) * 2);
        size_t soA = (size_t)(t0 + r)*K + k0 + c*8;
        size_t soW = (size_t)(o0 + r)*K + k0 + c*8;
        cp16(su + d,            Ah + soA);
        cp16(su + TILE_B + d,   Al + soA);
        cp16(su + 2*TILE_B + d, Wh + soW);
        cp16(su + 3*TILE_B + d, Wl + soW);
    }
    CP_COMMIT();
}

template<int MODE>
__global__ void __launch_bounds__(256, 2)
gemm_mma(const bf16* __restrict__ Ah, const bf16* __restrict__ Al,
         const bf16* __restrict__ Wh, const bf16* __restrict__ Wl,
         const float* __restrict__ bias, const float* __restrict__ res,
         const float* __restrict__ bng, const float* __restrict__ bnb,
         const float* __restrict__ bnm, const float* __restrict__ bnv,
         float* __restrict__ outf, bf16* __restrict__ oh, bf16* __restrict__ ol,
         int K, int N, float mult)
{
    extern __shared__ __align__(16) bf16 smb[];
    const uint32_t s0u = smem_u32(smb);

    const int tid = threadIdx.x;
    const int wid = tid >> 5, l = tid & 31;
    const int wm = wid & 3, wn = wid >> 2;    // warp tile: rows wm*32, cols wn*64
    const int t0 = blockIdx.y * 128;
    const int o0 = blockIdx.x * 128;

    float acc[2][8][4];
#pragma unroll
    for (int f = 0; f < 2; f++)
#pragma unroll
        for (int g = 0; g < 8; g++)
#pragma unroll
            for (int i = 0; i < 4; i++) acc[f][g][i] = 0.f;

    const int arow = l & 15;
    const int acol = (l >> 4) * 8;
    const int brow = ((l >> 4) << 3) + (l & 7);
    const int bcol = ((l >> 3) & 1) * 8;

    const int nch = K / KC;
    gemm_load_stage(Ah, Al, Wh, Wl, t0, o0, K, 0, s0u);

    for (int ch = 0; ch < nch; ++ch) {
        const int buf = ch & 1;
        __syncthreads();                               // stage buf^1 fully consumed
        if (ch + 1 < nch) {
            gemm_load_stage(Ah, Al, Wh, Wl, t0, o0, K, (ch+1)*KC,
                            s0u + (uint32_t)(buf ^ 1) * STAGE_B);
            CP_WAIT1();
        } else {
            CP_WAIT0();
        }
        __syncthreads();                               // stage buf visible to all

        const uint32_t sa = s0u + (uint32_t)buf * STAGE_B;
#pragma unroll
        for (int kk = 0; kk < 2; ++kk) {
            const int k0 = kk * 16;
            uint32_t ah[2][4], al2[2][4];
#pragma unroll
            for (int f = 0; f < 2; ++f) {
                uint32_t off = (uint32_t)(((wm*32 + f*16 + arow)*ASTR + k0 + acol) * 2);
                ldsm4(ah[f],  sa + off);
                ldsm4(al2[f], sa + TILE_B + off);
            }
#pragma unroll
            for (int gp = 0; gp < 4; ++gp) {
                uint32_t bh[4], bl[4];
                uint32_t off = (uint32_t)(((wn*64 + gp*16 + brow)*ASTR + k0 + bcol) * 2);
                ldsm4(bh, sa + 2*TILE_B + off);
                ldsm4(bl, sa + 3*TILE_B + off);
#pragma unroll
                for (int f = 0; f < 2; ++f) {
                    mma16816(acc[f][2*gp],   ah[f],  bh[0], bh[1]);
                    mma16816(acc[f][2*gp+1], ah[f],  bh[2], bh[3]);
                    mma16816(acc[f][2*gp],   ah[f],  bl[0], bl[1]);
                    mma16816(acc[f][2*gp+1], ah[f],  bl[2], bl[3]);
                    mma16816(acc[f][2*gp],   al2[f], bh[0], bh[1]);
                    mma16816(acc[f][2*gp+1], al2[f], bh[2], bh[3]);
                }
            }
        }
    }

    // ---- epilogue ----
    const int row_in = l >> 2, col_in = (l & 3) * 2;
#pragma unroll
    for (int f = 0; f < 2; ++f) {
        const int tb = t0 + wm*32 + f*16 + row_in;
#pragma unroll
        for (int g = 0; g < 8; ++g) {
            const int o = o0 + wn*64 + g*8 + col_in;
#pragma unroll
            for (int hhalf = 0; hhalf < 2; ++hhalf) {
                const int t = tb + hhalf*8;
                const float c0 = acc[f][g][hhalf*2 + 0];
                const float c1 = acc[f][g][hhalf*2 + 1];
                if (MODE == 0) {
                    float v0 = (c0 + bias[o]) * mult;
                    float v1 = (c1 + bias[o+1]) * mult;
                    bf16 h0, l0_, h1, l1_;
                    split_bf16(v0, h0, l0_); split_bf16(v1, h1, l1_);
                    *(uint32_t*)&oh[(size_t)t*N + o] = pack_bf2(h0, h1);
                    *(uint32_t*)&ol[(size_t)t*N + o] = pack_bf2(l0_, l1_);
                } else if (MODE == 1) {
#pragma unroll
                    for (int u = 0; u < 2; ++u) {
                        int oo = o + u;
                        size_t idx = (size_t)t*C_DIM + oo;
                        float val = (u ? c1 : c0) + bias[oo] + res[idx];
                        outf[idx] = val;
                        float inv = rsqrtf(bnv[oo] + BN_EPS);
                        float hb = (val - bnm[oo]) * inv * bng[oo] + bnb[oo];
                        bf16 hi, lo; split_bf16(hb, hi, lo);
                        oh[idx] = hi; ol[idx] = lo;
                    }
                } else if (MODE == 2) {
#pragma unroll
                    for (int u = 0; u < 2; ++u) {
                        int oo = o + u;
                        float val = (u ? c1 : c0) + bias[oo];
                        float ge = 0.5f * val * (1.0f + erff(val * 0.7071067811865475f));
                        size_t idx = (size_t)t*N + oo;
                        bf16 hi, lo; split_bf16(ge, hi, lo);
                        oh[idx] = hi; ol[idx] = lo;
                    }
                } else if (MODE == 3) { // NCHW final
                    const int bb2 = t / NPIX;
                    const int nn  = t - bb2 * NPIX;
#pragma unroll
                    for (int u = 0; u < 2; ++u) {
                        int oo = o + u;
                        float val = (u ? c1 : c0) + bias[oo] + res[(size_t)t*C_DIM + oo];
                        outf[((size_t)bb2*C_DIM + oo)*NPIX + nn] = val;
                    }
                } else { // MODE 4: V head-transposed [b][h][d][n]
                    const int bb2 = t / NPIX;
                    const int nn  = t - bb2 * NPIX;
#pragma unroll
                    for (int u = 0; u < 2; ++u) {
                        int oo = o + u;
                        int hh2 = oo / HDIM, dd = oo - hh2*HDIM;
                        float val = (u ? c1 : c0) + bias[oo];
                        bf16 hi, lo; split_bf16(val, hi, lo);
                        size_t dst = ((size_t)((bb2*HEADS + hh2)*HDIM + dd))*NPIX + nn;
                        oh[dst] = hi; ol[dst] = lo;
                    }
                }
            }
        }
    }
}

// ======================= flash-style mma attention (cp.async K/V pipeline) =======================
#define AQ_STR 56
#define AK_STR 56
#define AV_STR 72
#define K_STAGE_ELE (64*AK_STR)   // 3584
#define V_STAGE_ELE (48*AV_STR)   // 3456
// layout: Qh(7168) Ql(7168) | K stages [2][h,l] | V stages [2][h,l]
#define ATTN_SMEM ((2*128*AQ_STR + 4*K_STAGE_ELE + 4*V_STAGE_ELE) * 2)   // 84992 B
#define NBLK ((NPIX + 63) / 64)   // 13

__device__ __forceinline__ void attn_load_kv(
    const bf16* __restrict__ Kh, const bf16* __restrict__ Kl,
    const bf16* __restrict__ Vth, const bf16* __restrict__ Vtl,
    int b, int h, int n0,
    uint32_t kh_u, uint32_t kl_u, uint32_t vh_u, uint32_t vl_u)
{
    int tid = threadIdx.x;
    for (int idx = tid; idx < 64*6; idx += 256) {
        int r = idx / 6, cs = idx % 6;
        int t = b*NPIX + min(n0 + r, NPIX - 1);
        size_t so = (size_t)t*C_DIM + h*HDIM + cs*8;
        uint32_t d = (uint32_t)((r*AK_STR + cs*8) * 2);
        cp16(kh_u + d, Kh + so);
        cp16(kl_u + d, Kl + so);
    }
    for (int idx = tid; idx < 48*8; idx += 256) {
        int r = idx / 8, cs = idx % 8;
        size_t so = ((size_t)((b*HEADS + h)*HDIM + r))*NPIX + n0 + cs*8;
        uint32_t d = (uint32_t)((r*AV_STR + cs*8) * 2);
        cp16(vh_u + d, Vth + so);
        cp16(vl_u + d, Vtl + so);
    }
    CP_COMMIT();
}

__global__ void __launch_bounds__(256)
attn_mma(const bf16* __restrict__ Qh, const bf16* __restrict__ Ql,
         const bf16* __restrict__ Kh, const bf16* __restrict__ Kl,
         const bf16* __restrict__ Vth, const bf16* __restrict__ Vtl,
         bf16* __restrict__ AOh, bf16* __restrict__ AOl)
{
    extern __shared__ __align__(16) bf16 sm_[];
    bf16* sQh = sm_;
    bf16* sQl = sQh + 128*AQ_STR;
    bf16* sK  = sQl + 128*AQ_STR;      // [stage][h/l]
    bf16* sV  = sK + 4*K_STAGE_ELE;

    const int tid = threadIdx.x, w = tid >> 5, ln = tid & 31;
    const int qb = blockIdx.x, h = blockIdx.y, b = blockIdx.z;
    const int q0 = qb * 128;

    uint32_t kstage_u[2][2], vstage_u[2][2];
#pragma unroll
    for (int s = 0; s < 2; s++) {
        kstage_u[s][0] = smem_u32(sK + s*2*K_STAGE_ELE);
        kstage_u[s][1] = kstage_u[s][0] + K_STAGE_ELE*2;
        vstage_u[s][0] = smem_u32(sV + s*2*V_STAGE_ELE);
        vstage_u[s][1] = vstage_u[s][0] + V_STAGE_ELE*2;
    }

    // prefetch K/V block 0 while Q loads
    attn_load_kv(Kh, Kl, Vth, Vtl, b, h, 0, kstage_u[0][0], kstage_u[0][1],
                 vstage_u[0][0], vstage_u[0][1]);

    // ---- load Q tile (rows clamped to image) ----
    for (int idx = tid; idx < 128*6; idx += 256) {
        int r = idx / 6, cs = idx % 6;
        int t = b*NPIX + min(q0 + r, NPIX - 1);
        const bf16* ph_ = Qh + (size_t)t*C_DIM + h*HDIM;
        const bf16* pl_ = Ql + (size_t)t*C_DIM + h*HDIM;
        *(uint4*)(sQh + r*AQ_STR + cs*8) = *((const uint4*)ph_ + cs);
        *(uint4*)(sQl + r*AQ_STR + cs*8) = *((const uint4*)pl_ + cs);
    }
    __syncthreads();

    // ---- Q fragments (persistent) ----
    const int arow = ln & 15, acol = (ln >> 4) * 8;
    const int brow = ((ln >> 4) << 3) + (ln & 7), bcol = ((ln >> 3) & 1) * 8;
    uint32_t qfh[3][4], qfl[3][4];
    {
        const uint32_t qb_h = smem_u32(sQh), qb_l = smem_u32(sQl);
#pragma unroll
        for (int kc = 0; kc < 3; kc++) {
            uint32_t off = (uint32_t)(((w*16 + arow)*AQ_STR + kc*16 + acol) * 2);
            ldsm4(qfh[kc], qb_h + off);
            ldsm4(qfl[kc], qb_l + off);
        }
    }

    float rm0 = -1e30f, rm1 = -1e30f;   // running max (rows ln/4, ln/4+8)
    float rl0 = 0.f,    rl1 = 0.f;      // running sum
    float O[6][4];
#pragma unroll
    for (int j = 0; j < 6; j++)
#pragma unroll
        for (int i = 0; i < 4; i++) O[j][i] = 0.f;

    for (int it = 0; it < NBLK; ++it) {
        const int buf = it & 1;
        const int n0 = it * 64;
        __syncthreads();                            // stage buf^1 fully consumed
        if (it + 1 < NBLK) {
            attn_load_kv(Kh, Kl, Vth, Vtl, b, h, (it+1)*64,
                         kstage_u[buf^1][0], kstage_u[buf^1][1],
                         vstage_u[buf^1][0], vstage_u[buf^1][1]);
            CP_WAIT1();
        } else {
            CP_WAIT0();
        }
        __syncthreads();

        const uint32_t kb_h = kstage_u[buf][0], kb_l = kstage_u[buf][1];
        const uint32_t vb_h = vstage_u[buf][0], vb_l = vstage_u[buf][1];

        // ---- S = Q K^T (8 n-tiles of 8 keys) ----
        float s[8][4];
#pragma unroll
        for (int j = 0; j < 8; j++)
#pragma unroll
            for (int i = 0; i < 4; i++) s[j][i] = 0.f;

#pragma unroll
        for (int kc = 0; kc < 3; kc++) {
#pragma unroll
            for (int g = 0; g < 4; g++) {
                uint32_t off = (uint32_t)(((g*16 + brow)*AK_STR + kc*16 + bcol) * 2);
                uint32_t kh4[4], kl4[4];
                ldsm4(kh4, kb_h + off);
                ldsm4(kl4, kb_l + off);
                mma16816(s[2*g],   qfh[kc], kh4[0], kh4[1]);
                mma16816(s[2*g+1], qfh[kc], kh4[2], kh4[3]);
                mma16816(s[2*g],   qfh[kc], kl4[0], kl4[1]);
                mma16816(s[2*g+1], qfh[kc], kl4[2], kl4[3]);
                mma16816(s[2*g],   qfl[kc], kh4[0], kh4[1]);
                mma16816(s[2*g+1], qfl[kc], kh4[2], kh4[3]);
            }
        }

        // ---- mask tail keys ----
        if (n0 + 64 > NPIX) {
            int c2 = 2*(ln & 3);
#pragma unroll
            for (int j = 0; j < 8; j++) {
                int col = n0 + 8*j + c2;
                if (col >= NPIX) { s[j][0] = s[j][1] = s[j][2] = s[j][3] = -1e30f; }
            }
        }

        // ---- online softmax ----
        float bm0 = -1e30f, bm1 = -1e30f;
#pragma unroll
        for (int j = 0; j < 8; j++) {
            bm0 = fmaxf(bm0, fmaxf(s[j][0], s[j][1]));
            bm1 = fmaxf(bm1, fmaxf(s[j][2], s[j][3]));
        }
        bm0 = fmaxf(bm0, __shfl_xor_sync(0xffffffffu, bm0, 1));
        bm0 = fmaxf(bm0, __shfl_xor_sync(0xffffffffu, bm0, 2));
        bm1 = fmaxf(bm1, __shfl_xor_sync(0xffffffffu, bm1, 1));
        bm1 = fmaxf(bm1, __shfl_xor_sync(0xffffffffu, bm1, 2));
        float nm0 = fmaxf(rm0, bm0), nm1 = fmaxf(rm1, bm1);
        float sc0 = __expf(rm0 - nm0), sc1 = __expf(rm1 - nm1);
        rm0 = nm0; rm1 = nm1;
        float bs0 = 0.f, bs1 = 0.f;
#pragma unroll
        for (int j = 0; j < 8; j++) {
            s[j][0] = __expf(s[j][0] - nm0);
            s[j][1] = __expf(s[j][1] - nm0);
            s[j][2] = __expf(s[j][2] - nm1);
            s[j][3] = __expf(s[j][3] - nm1);
            bs0 += s[j][0] + s[j][1];
            bs1 += s[j][2] + s[j][3];
        }
        bs0 += __shfl_xor_sync(0xffffffffu, bs0, 1);
        bs0 += __shfl_xor_sync(0xffffffffu, bs0, 2);
        bs1 += __shfl_xor_sync(0xffffffffu, bs1, 1);
        bs1 += __shfl_xor_sync(0xffffffffu, bs1, 2);
        rl0 = rl0*sc0 + bs0;
        rl1 = rl1*sc1 + bs1;
#pragma unroll
        for (int j = 0; j < 6; j++) {
            O[j][0] *= sc0; O[j][1] *= sc0;
            O[j][2] *= sc1; O[j][3] *= sc1;
        }

        // ---- O += P V (P fragments re-packed from S regs, split hi/lo) ----
#pragma unroll
        for (int kc = 0; kc < 4; kc++) {
            uint32_t ph[4], pl[4];
            {
                bf16 h0, l0_, h1, l1_;
                split_bf16(s[2*kc][0], h0, l0_); split_bf16(s[2*kc][1], h1, l1_);
                ph[0] = pack_bf2(h0, h1); pl[0] = pack_bf2(l0_, l1_);
                split_bf16(s[2*kc][2], h0, l0_); split_bf16(s[2*kc][3], h1, l1_);
                ph[1] = pack_bf2(h0, h1); pl[1] = pack_bf2(l0_, l1_);
                split_bf16(s[2*kc+1][0], h0, l0_); split_bf16(s[2*kc+1][1], h1, l1_);
                ph[2] = pack_bf2(h0, h1); pl[2] = pack_bf2(l0_, l1_);
                split_bf16(s[2*kc+1][2], h0, l0_); split_bf16(s[2*kc+1][3], h1, l1_);
                ph[3] = pack_bf2(h0, h1); pl[3] = pack_bf2(l0_, l1_);
            }
#pragma unroll
            for (int dg = 0; dg < 3; dg++) {
                uint32_t off = (uint32_t)(((dg*16 + brow)*AV_STR + kc*16 + bcol) * 2);
                uint32_t vh4[4], vl4[4];
                ldsm4(vh4, vb_h + off);
                ldsm4(vl4, vb_l + off);
                mma16816(O[2*dg],   ph, vh4[0], vh4[1]);
                mma16816(O[2*dg+1], ph, vh4[2], vh4[3]);
                mma16816(O[2*dg],   ph, vl4[0], vl4[1]);
                mma16816(O[2*dg+1], ph, vl4[2], vl4[3]);
                mma16816(O[2*dg],   pl, vh4[0], vh4[1]);
                mma16816(O[2*dg+1], pl, vh4[2], vh4[3]);
            }
        }
    }

    // ---- epilogue: normalize + split-store ----
    float inv0 = 1.f / rl0, inv1 = 1.f / rl1;
    int r0 = q0 + w*16 + (ln >> 2);
    int r1 = r0 + 8;
    int cbase = h*HDIM + 2*(ln & 3);
#pragma unroll
    for (int jn = 0; jn < 6; jn++) {
        int c = cbase + 8*jn;
        if (r0 < NPIX) {
            size_t idx = (size_t)(b*NPIX + r0)*C_DIM + c;
            bf16 h0, l0_, h1, l1_;
            split_bf16(O[jn][0]*inv0, h0, l0_);
            split_bf16(O[jn][1]*inv0, h1, l1_);
            *(uint32_t*)&AOh[idx] = pack_bf2(h0, h1);
            *(uint32_t*)&AOl[idx] = pack_bf2(l0_, l1_);
        }
        if (r1 < NPIX) {
            size_t idx = (size_t)(b*NPIX + r1)*C_DIM + c;
            bf16 h0, l0_, h1, l1_;
            split_bf16(O[jn][2]*inv1, h0, l0_);
            split_bf16(O[jn][3]*inv1, h1, l1_);
            *(uint32_t*)&AOh[idx] = pack_bf2(h0, h1);
            *(uint32_t*)&AOl[idx] = pack_bf2(l0_, l1_);
        }
    }
}

// ---------------- host ----------------
extern "C" void kernel_launch(void* const* d_in, const int* in_sizes, int n_in,
                              void* d_out, int out_size)
{
    const float* x       = (const float*)d_in[0];
    const float* local_w = (const float*)d_in[1];
    const float* local_b = (const float*)d_in[2];
    const float* bn1_g   = (const float*)d_in[3];
    const float* bn1_b   = (const float*)d_in[4];
    const float* bn1_m   = (const float*)d_in[5];
    const float* bn1_v   = (const float*)d_in[6];
    const float* q_w     = (const float*)d_in[7];
    const float* q_b     = (const float*)d_in[8];
    const float* k_w     = (const float*)d_in[9];
    const float* k_b     = (const float*)d_in[10];
    const float* v_w     = (const float*)d_in[11];
    const float* v_b     = (const float*)d_in[12];
    const float* proj_w  = (const float*)d_in[13];
    const float* proj_b  = (const float*)d_in[14];
    const float* ffn1_w  = (const float*)d_in[15];
    const float* ffn1_b  = (const float*)d_in[16];
    const float* ffn2_w  = (const float*)d_in[17];
    const float* ffn2_b  = (const float*)d_in[18];
    const float* bn2_g   = (const float*)d_in[19];
    const float* bn2_b   = (const float*)d_in[20];
    const float* bn2_m   = (const float*)d_in[21];
    const float* bn2_v   = (const float*)d_in[22];

    float *lx, *r;
    bf16 *lxh, *lxl, *qh, *ql, *kh, *kl, *vth, *vtl, *aoh, *aol, *hh, *hl, *f1h, *f1l;
    bf16 *qwh, *qwl, *kwh, *kwl, *vwh, *vwl, *pwh, *pwl, *w1h, *w1l, *w2h, *w2l;
    cudaGetSymbolAddress((void**)&lx,  g_lx);
    cudaGetSymbolAddress((void**)&lxh, g_lxh);
    cudaGetSymbolAddress((void**)&lxl, g_lxl);
    cudaGetSymbolAddress((void**)&qh,  g_qh);
    cudaGetSymbolAddress((void**)&ql,  g_ql);
    cudaGetSymbolAddress((void**)&kh,  g_kh);
    cudaGetSymbolAddress((void**)&kl,  g_kl);
    cudaGetSymbolAddress((void**)&vth, g_vth);
    cudaGetSymbolAddress((void**)&vtl, g_vtl);
    cudaGetSymbolAddress((void**)&aoh, g_aoh);
    cudaGetSymbolAddress((void**)&aol, g_aol);
    cudaGetSymbolAddress((void**)&r,   g_r);
    cudaGetSymbolAddress((void**)&hh,  g_hh);
    cudaGetSymbolAddress((void**)&hl,  g_hl);
    cudaGetSymbolAddress((void**)&f1h, g_f1h);
    cudaGetSymbolAddress((void**)&f1l, g_f1l);
    cudaGetSymbolAddress((void**)&qwh, g_qwh); cudaGetSymbolAddress((void**)&qwl, g_qwl);
    cudaGetSymbolAddress((void**)&kwh, g_kwh); cudaGetSymbolAddress((void**)&kwl, g_kwl);
    cudaGetSymbolAddress((void**)&vwh, g_vwh); cudaGetSymbolAddress((void**)&vwl, g_vwl);
    cudaGetSymbolAddress((void**)&pwh, g_pwh); cudaGetSymbolAddress((void**)&pwl, g_pwl);
    cudaGetSymbolAddress((void**)&w1h, g_w1h); cudaGetSymbolAddress((void**)&w1l, g_w1l);
    cudaGetSymbolAddress((void**)&w2h, g_w2h); cudaGetSymbolAddress((void**)&w2l, g_w2l);

    cudaFuncSetAttribute(gemm_mma<0>, cudaFuncAttributeMaxDynamicSharedMemorySize, GEMM_SMEM);
    cudaFuncSetAttribute(gemm_mma<1>, cudaFuncAttributeMaxDynamicSharedMemorySize, GEMM_SMEM);
    cudaFuncSetAttribute(gemm_mma<2>, cudaFuncAttributeMaxDynamicSharedMemorySize, GEMM_SMEM);
    cudaFuncSetAttribute(gemm_mma<3>, cudaFuncAttributeMaxDynamicSharedMemorySize, GEMM_SMEM);
    cudaFuncSetAttribute(gemm_mma<4>, cudaFuncAttributeMaxDynamicSharedMemorySize, GEMM_SMEM);
    cudaFuncSetAttribute(attn_mma,    cudaFuncAttributeMaxDynamicSharedMemorySize, ATTN_SMEM);

    // 0. all weight conversions in one launch
    cvt_all_kernel<<<(4*NW + 2*NF + 255)/256, 256>>>(
        q_w, qwh, qwl, k_w, kwh, kwl, v_w, vwh, vwl,
        proj_w, pwh, pwl, ffn1_w, w1h, w1l, ffn2_w, w2h, w2l);

    // 1. fused depthwise conv + BN1 + transpose -> token-major (+ bf16 split)
    conv_tokens_kernel<<<dim3(25, 12, BATCH), dim3(32, 8)>>>(
        x, local_w, local_b, bn1_g, bn1_b, bn1_m, bn1_v);

    dim3 g384(3, 98), g1536(12, 98);
    const float scale = 0.14433756729740643f;   // 48^-0.5

    // 2. QKV: Q (scale folded) / K -> [t][c] hi/lo; V -> [b][h][d][n] hi/lo
    gemm_mma<0><<<g384, 256, GEMM_SMEM>>>(lxh, lxl, qwh, qwl, q_b, nullptr,
        nullptr, nullptr, nullptr, nullptr, nullptr, qh, ql, C_DIM, C_DIM, scale);
    gemm_mma<0><<<g384, 256, GEMM_SMEM>>>(lxh, lxl, kwh, kwl, k_b, nullptr,
        nullptr, nullptr, nullptr, nullptr, nullptr, kh, kl, C_DIM, C_DIM, 1.0f);
    gemm_mma<4><<<g384, 256, GEMM_SMEM>>>(lxh, lxl, vwh, vwl, v_b, nullptr,
        nullptr, nullptr, nullptr, nullptr, nullptr, vth, vtl, C_DIM, C_DIM, 1.0f);

    // 3. flash attention (tensor cores, pipelined K/V) -> ao hi/lo
    attn_mma<<<dim3(7, HEADS, BATCH), 256, ATTN_SMEM>>>(qh, ql, kh, kl, vth, vtl, aoh, aol);

    // 4. proj + residual(lx) -> r (f32); BN2 -> h (hi/lo)
    gemm_mma<1><<<g384, 256, GEMM_SMEM>>>(aoh, aol, pwh, pwl, proj_b, lx,
        bn2_g, bn2_b, bn2_m, bn2_v, r, hh, hl, C_DIM, C_DIM, 1.0f);

    // 5. FFN1 + gelu -> f1 (hi/lo)
    gemm_mma<2><<<g1536, 256, GEMM_SMEM>>>(hh, hl, w1h, w1l, ffn1_b, nullptr,
        nullptr, nullptr, nullptr, nullptr, nullptr, f1h, f1l, C_DIM, FFN_DIM, 1.0f);

    // 6. FFN2 + residual(r), NCHW output
    gemm_mma<3><<<g384, 256, GEMM_SMEM>>>(f1h, f1l, w2h, w2l, ffn2_b, r,
        nullptr, nullptr, nullptr, nullptr, (float*)d_out, nullptr, nullptr, FFN_DIM, C_DIM, 1.0f);
}